// round 13
// baseline (speedup 1.0000x reference)
#include <cuda_runtime.h>

// ---------------------------------------------------------------------------
// BottleNeck MHSA: B=16, C=512, H=W=32 (N=1024), NH=8, DK=64.
// All fp32. 5 kernels: transpose_w, qkv(128x128x16 dbuf), transpose_v,
// flash(64q x 128k, 4x8 micro, 2 CTA/SM), out_proj.
// ---------------------------------------------------------------------------

#define Bsz 16
#define Cch 512
#define NPIX 1024
#define NHh 8
#define DKd 64
#define BH 128

__device__ float g_wt[4 * 512 * 512];        // transposed weights (c, o) x {q,k,v,o}
__device__ float g_q [BH * DKd * NPIX];      // (bh, dk, n)
__device__ float g_k [BH * DKd * NPIX];      // (bh, dk, n)
__device__ float g_vt[BH * DKd * NPIX];      // (bh, dk, n)  pre-transpose
__device__ float g_v [BH * NPIX * DKd];      // (bh, n, dk)
__device__ float g_o [Bsz * Cch * NPIX];     // (b, c=nh*64+d, n)

// ---------------------------------------------------------------------------
// Kernel 0: transpose the four 512x512 weight matrices into (c, o) layout.
// ---------------------------------------------------------------------------
__global__ __launch_bounds__(256) void transpose_w_kernel(
    const float* __restrict__ wq, const float* __restrict__ wk,
    const float* __restrict__ wv, const float* __restrict__ wo)
{
    __shared__ float t[32][33];
    const float* w = (blockIdx.z == 0) ? wq : (blockIdx.z == 1) ? wk
                   : (blockIdx.z == 2) ? wv : wo;
    float* wt = g_wt + (size_t)blockIdx.z * 512 * 512;
    const int c0 = blockIdx.x * 32, o0 = blockIdx.y * 32;
    const int tx = threadIdx.x & 31, ty = threadIdx.x >> 5;
#pragma unroll
    for (int i = 0; i < 4; i++)
        t[ty + i * 8][tx] = w[(o0 + ty + i * 8) * 512 + c0 + tx];
    __syncthreads();
#pragma unroll
    for (int i = 0; i < 4; i++)
        wt[(c0 + ty + i * 8) * 512 + o0 + tx] = t[tx][ty + i * 8];
}

// ---------------------------------------------------------------------------
// Kernel 1: QKV projection. 128x128 tile, K-tile 16, 256 thr, 8x8 microtile,
// double-buffered smem with register prefetch. All outputs dk-major.
// ---------------------------------------------------------------------------
__global__ __launch_bounds__(256, 2) void qkv_kernel(const float* __restrict__ x)
{
    const int nt = blockIdx.x, mt = blockIdx.y;
    const int z = blockIdx.z;
    const int b = z / 3, wsel = z - 3 * b;
    const int o0 = mt * 128, n0 = nt * 128;
    const float* wt = g_wt + (size_t)wsel * 512 * 512;
    const float* xb = x + (size_t)b * Cch * NPIX;

    __shared__ float As[2][16 * 128];
    __shared__ float Bs[2][16 * 128];

    const int tid = threadIdx.x;
    const int tx = tid & 15, ty = tid >> 4;

    float acc[8][8];
#pragma unroll
    for (int r = 0; r < 8; r++)
#pragma unroll
        for (int c = 0; c < 8; c++) acc[r][c] = 0.f;

    const int lkk0 = (tid + 0 * 256) >> 5, lc40 = ((tid + 0 * 256) & 31) * 4;
    const int lkk1 = (tid + 1 * 256) >> 5, lc41 = ((tid + 1 * 256) & 31) * 4;

    float4 pa0, pa1, pb0, pb1;
    pa0 = *(const float4*)&wt[lkk0 * 512 + o0 + lc40];
    pa1 = *(const float4*)&wt[lkk1 * 512 + o0 + lc41];
    pb0 = *(const float4*)&xb[lkk0 * 1024 + n0 + lc40];
    pb1 = *(const float4*)&xb[lkk1 * 1024 + n0 + lc41];
    *(float4*)&As[0][lkk0 * 128 + lc40] = pa0;
    *(float4*)&As[0][lkk1 * 128 + lc41] = pa1;
    *(float4*)&Bs[0][lkk0 * 128 + lc40] = pb0;
    *(float4*)&Bs[0][lkk1 * 128 + lc41] = pb1;

#pragma unroll 1
    for (int kt = 0; kt < 32; kt++) {
        __syncthreads();
        const int cur = kt & 1;
        if (kt < 31) {
            const int c0 = (kt + 1) * 16;
            pa0 = *(const float4*)&wt[(c0 + lkk0) * 512 + o0 + lc40];
            pa1 = *(const float4*)&wt[(c0 + lkk1) * 512 + o0 + lc41];
            pb0 = *(const float4*)&xb[(c0 + lkk0) * 1024 + n0 + lc40];
            pb1 = *(const float4*)&xb[(c0 + lkk1) * 1024 + n0 + lc41];
        }
#pragma unroll 8
        for (int kk = 0; kk < 16; kk++) {
            float4 a0 = *(float4*)&As[cur][kk * 128 + ty * 4];
            float4 a1 = *(float4*)&As[cur][kk * 128 + 64 + ty * 4];
            float4 b0 = *(float4*)&Bs[cur][kk * 128 + tx * 4];
            float4 b1 = *(float4*)&Bs[cur][kk * 128 + 64 + tx * 4];
            float av[8] = {a0.x, a0.y, a0.z, a0.w, a1.x, a1.y, a1.z, a1.w};
            float bv[8] = {b0.x, b0.y, b0.z, b0.w, b1.x, b1.y, b1.z, b1.w};
#pragma unroll
            for (int r = 0; r < 8; r++)
#pragma unroll
                for (int c = 0; c < 8; c++) acc[r][c] += av[r] * bv[c];
        }
        if (kt < 31) {
            const int nxt = cur ^ 1;
            *(float4*)&As[nxt][lkk0 * 128 + lc40] = pa0;
            *(float4*)&As[nxt][lkk1 * 128 + lc41] = pa1;
            *(float4*)&Bs[nxt][lkk0 * 128 + lc40] = pb0;
            *(float4*)&Bs[nxt][lkk1 * 128 + lc41] = pb1;
        }
    }

    float* dst = (wsel == 0) ? g_q : (wsel == 1) ? g_k : g_vt;
#pragma unroll
    for (int r = 0; r < 8; r++) {
        const int o = o0 + ((r < 4) ? (ty * 4 + r) : (64 + ty * 4 + r - 4));
        const int nh = o & 7, dk = o >> 3;
        const int bh = b * 8 + nh;
        float* p = dst + ((size_t)bh * 64 + dk) * 1024 + n0;
        *(float4*)&p[tx * 4]      = make_float4(acc[r][0], acc[r][1], acc[r][2], acc[r][3]);
        *(float4*)&p[64 + tx * 4] = make_float4(acc[r][4], acc[r][5], acc[r][6], acc[r][7]);
    }
}

// ---------------------------------------------------------------------------
// Kernel 2: transpose V (bh, dk, n) -> (bh, n, dk).
// ---------------------------------------------------------------------------
__global__ __launch_bounds__(256) void transpose_v_kernel()
{
    __shared__ float t[64][65];
    const int bh = blockIdx.y, n0 = blockIdx.x * 64;
    const float* src = g_vt + (size_t)bh * 64 * 1024;
    float* dst = g_v + (size_t)bh * 1024 * 64;
#pragma unroll
    for (int i = 0; i < 16; i++) {
        int id = threadIdx.x + i * 256;
        int d = id >> 6, n = id & 63;
        t[d][n] = src[d * 1024 + n0 + n];
    }
    __syncthreads();
#pragma unroll
    for (int i = 0; i < 16; i++) {
        int id = threadIdx.x + i * 256;
        int n = id >> 6, d = id & 63;
        dst[(size_t)(n0 + n) * 64 + d] = t[d][n];
    }
}

// ---------------------------------------------------------------------------
// Kernel 3: flash attention. Q-tile 64, K-tile 128, 256 thr, 4x8 micro,
// 2 CTAs/SM (99 KB smem, <=128 regs). K and V share one smem buffer.
// ---------------------------------------------------------------------------
#define FL_QS  0                       // [64 dk][68]  (padded, col-read safe)
#define FL_KV  (FL_QS + 64 * 68)       // K: [64 dk][128k]  then V: [128k][64d]
#define FL_PS  (FL_KV + 8192)          // [64 q][132]
#define FL_RBH (FL_PS + 64 * 132)      // [64 q][33]
#define FL_RBW (FL_RBH + 64 * 33)      // [64 q][36]
#define FL_TOT_FLOATS (FL_RBW + 64 * 36)
#define FL_SMEM_BYTES (FL_TOT_FLOATS * 4)

__global__ __launch_bounds__(256, 2) void flash_kernel(
    const float* __restrict__ rel_h, const float* __restrict__ rel_w)
{
    extern __shared__ float sm[];
    float* Qs  = sm + FL_QS;
    float* KV  = sm + FL_KV;
    float* Ps  = sm + FL_PS;
    float* RBh = sm + FL_RBH;
    float* RBw = sm + FL_RBW;

    const int qt = blockIdx.x;     // 0..15
    const int bh = blockIdx.y;     // 0..127
    const int b = bh >> 3, nh = bh & 7;
    const int q0 = qt * 64;
    const int tid = threadIdx.x, tx = tid & 15, ty = tid >> 4;

    const float* qg = g_q + (size_t)bh * 64 * 1024;
    const float* kg = g_k + (size_t)bh * 64 * 1024;
    const float* vg = g_v + (size_t)bh * 1024 * 64;

    // Q load (64dk x 64q), scaled by 1/8 (scales both energy and bias)
#pragma unroll
    for (int i = 0; i < 4; i++) {
        int id = tid + i * 256;
        int dk = id >> 4, c4 = (id & 15) * 4;
        float4 t = *(const float4*)&qg[dk * 1024 + q0 + c4];
        t.x *= 0.125f; t.y *= 0.125f; t.z *= 0.125f; t.w *= 0.125f;
        *(float4*)&Qs[dk * 68 + c4] = t;
    }
    __syncthreads();

    // Bias tables. Thread owns one q-row column of Qs (cached in regs) and
    // computes 16 dots: RBh[p][c] = q_p.rel_h[c-xp+31], RBw[p][j] = q_p.rel_w[j-yp+31]
    {
        const int p = tid & 63;
        const int cbase = (tid >> 6) * 16;   // 0,16,32,48
        float myq[64];
#pragma unroll
        for (int dk = 0; dk < 64; dk++) myq[dk] = Qs[dk * 68 + p];
        const int xp = qt * 2 + (p >> 5);
        const int yp = p & 31;
#pragma unroll
        for (int j = 0; j < 16; j++) {
            const int c = cbase + j;
            const float* rr = (c < 32) ? (rel_h + (c - xp + 31) * 64)
                                       : (rel_w + ((c - 32) - yp + 31) * 64);
            float s = 0.f;
#pragma unroll
            for (int k4 = 0; k4 < 16; k4++) {
                float4 r4 = *(const float4*)&rr[k4 * 4];
                s += myq[k4 * 4 + 0] * r4.x + myq[k4 * 4 + 1] * r4.y
                   + myq[k4 * 4 + 2] * r4.z + myq[k4 * 4 + 3] * r4.w;
            }
            if (c < 32) RBh[p * 33 + c] = s;
            else        RBw[p * 36 + (c - 32)] = s;
        }
    }

    float m_[4], l_[4], oa[4][4];
#pragma unroll
    for (int r = 0; r < 4; r++) {
        m_[r] = -1e30f; l_[r] = 0.f;
#pragma unroll
        for (int d = 0; d < 4; d++) oa[r][d] = 0.f;
    }

    const int j0 = (tx * 4) & 31;     // rel-w column group (same for both key halves)

#pragma unroll 1
    for (int kt = 0; kt < 8; kt++) {
        __syncthreads();              // KV buffer free (prev PV done), Ps free
        // Load K tile (dk-major) into KV
#pragma unroll
        for (int i = 0; i < 8; i++) {
            int id = tid + i * 256;
            int r_ = id >> 5, c4 = (id & 31) * 4;
            *(float4*)&KV[r_ * 128 + c4] =
                *(const float4*)&kg[r_ * 1024 + kt * 128 + c4];
        }
        __syncthreads();

        // S = Q^T K : 4q x 8k per thread
        float s[4][8];
#pragma unroll
        for (int r = 0; r < 4; r++)
#pragma unroll
            for (int c = 0; c < 8; c++) s[r][c] = 0.f;
#pragma unroll 8
        for (int kk = 0; kk < 64; kk++) {
            float4 a4 = *(float4*)&Qs[kk * 68 + ty * 4];
            float4 b0 = *(float4*)&KV[kk * 128 + tx * 4];
            float4 b1 = *(float4*)&KV[kk * 128 + 64 + tx * 4];
            float av[4] = {a4.x, a4.y, a4.z, a4.w};
            float bv[8] = {b0.x, b0.y, b0.z, b0.w, b1.x, b1.y, b1.z, b1.w};
#pragma unroll
            for (int r = 0; r < 4; r++)
#pragma unroll
                for (int c = 0; c < 8; c++) s[r][c] += av[r] * bv[c];
        }

        // bias add: keys c<4 -> klocal=tx*4+c ; c>=4 -> 64+tx*4+(c-4)
        const int iA = kt * 4 + (tx >> 3);
        const int iB = iA + 2;
#pragma unroll
        for (int r = 0; r < 4; r++) {
            const int row = ty * 4 + r;
            float hA = RBh[row * 33 + iA];
            float hB = RBh[row * 33 + iB];
            float4 w4 = *(float4*)&RBw[row * 36 + j0];
            float wv[4] = {w4.x, w4.y, w4.z, w4.w};
#pragma unroll
            for (int c = 0; c < 4; c++) s[r][c]     += hA + wv[c];
#pragma unroll
            for (int c = 0; c < 4; c++) s[r][4 + c] += hB + wv[c];
        }

        // online softmax (16-lane groups span all 128 keys)
#pragma unroll
        for (int r = 0; r < 4; r++) {
            float tm = s[r][0];
#pragma unroll
            for (int c = 1; c < 8; c++) tm = fmaxf(tm, s[r][c]);
#pragma unroll
            for (int o = 8; o >= 1; o >>= 1)
                tm = fmaxf(tm, __shfl_xor_sync(0xffffffffu, tm, o));
            float mnew = fmaxf(m_[r], tm);
            float sc = __expf(m_[r] - mnew);
            float rs = 0.f;
#pragma unroll
            for (int c = 0; c < 8; c++) { s[r][c] = __expf(s[r][c] - mnew); rs += s[r][c]; }
#pragma unroll
            for (int o = 8; o >= 1; o >>= 1)
                rs += __shfl_xor_sync(0xffffffffu, rs, o);
            l_[r] = l_[r] * sc + rs;
            m_[r] = mnew;
#pragma unroll
            for (int d = 0; d < 4; d++) oa[r][d] *= sc;
        }

        // store P (q-major)
#pragma unroll
        for (int r = 0; r < 4; r++) {
            const int row = ty * 4 + r;
            *(float4*)&Ps[row * 132 + tx * 4] =
                make_float4(s[r][0], s[r][1], s[r][2], s[r][3]);
            *(float4*)&Ps[row * 132 + 64 + tx * 4] =
                make_float4(s[r][4], s[r][5], s[r][6], s[r][7]);
        }
        __syncthreads();              // K reads done -> safe to overwrite with V

        // Load V tile (key-major) into KV
#pragma unroll
        for (int i = 0; i < 8; i++) {
            int id = tid + i * 256;
            int r_ = id >> 4, c4 = (id & 15) * 4;
            *(float4*)&KV[r_ * 64 + c4] =
                *(const float4*)&vg[(size_t)(kt * 128 + r_) * 64 + c4];
        }
        __syncthreads();

        // O += P @ V : 4q x 4d per thread over 128 keys (4 at a time)
#pragma unroll 4
        for (int c4 = 0; c4 < 32; c4++) {
            float4 vf0 = *(float4*)&KV[(c4 * 4 + 0) * 64 + tx * 4];
            float4 vf1 = *(float4*)&KV[(c4 * 4 + 1) * 64 + tx * 4];
            float4 vf2 = *(float4*)&KV[(c4 * 4 + 2) * 64 + tx * 4];
            float4 vf3 = *(float4*)&KV[(c4 * 4 + 3) * 64 + tx * 4];
#pragma unroll
            for (int r = 0; r < 4; r++) {
                float4 pf = *(float4*)&Ps[(ty * 4 + r) * 132 + c4 * 4];
                oa[r][0] += pf.x * vf0.x + pf.y * vf1.x + pf.z * vf2.x + pf.w * vf3.x;
                oa[r][1] += pf.x * vf0.y + pf.y * vf1.y + pf.z * vf2.y + pf.w * vf3.y;
                oa[r][2] += pf.x * vf0.z + pf.y * vf1.z + pf.z * vf2.z + pf.w * vf3.z;
                oa[r][3] += pf.x * vf0.w + pf.y * vf1.w + pf.z * vf2.w + pf.w * vf3.w;
            }
        }
    }

    // epilogue: normalize, stage via Ps, write coalesced (d-major rows)
#pragma unroll
    for (int r = 0; r < 4; r++) {
        float il = 1.f / l_[r];
        *(float4*)&Ps[(ty * 4 + r) * 132 + tx * 4] =
            make_float4(oa[r][0] * il, oa[r][1] * il, oa[r][2] * il, oa[r][3] * il);
    }
    __syncthreads();
    float* og = g_o + ((size_t)b * 512 + nh * 64) * 1024 + q0;
#pragma unroll
    for (int i = 0; i < 16; i++) {
        int id = tid + i * 256;
        int q = id & 63, d = id >> 6;
        og[d * 1024 + q] = Ps[q * 132 + d];
    }
}

// ---------------------------------------------------------------------------
// Kernel 4: output projection + bias.
// ---------------------------------------------------------------------------
__global__ __launch_bounds__(256, 2) void out_proj_kernel(
    const float* __restrict__ bo, float* __restrict__ out)
{
    const int nt = blockIdx.x, mt = blockIdx.y, b = blockIdx.z;
    const int o0 = mt * 128, n0 = nt * 128;
    const float* wt = g_wt + (size_t)3 * 512 * 512;
    const float* xb = g_o + (size_t)b * Cch * NPIX;

    __shared__ float As[2][16 * 128];
    __shared__ float Bs[2][16 * 128];

    const int tid = threadIdx.x;
    const int tx = tid & 15, ty = tid >> 4;

    float acc[8][8];
#pragma unroll
    for (int r = 0; r < 8; r++)
#pragma unroll
        for (int c = 0; c < 8; c++) acc[r][c] = 0.f;

    const int lkk0 = (tid + 0 * 256) >> 5, lc40 = ((tid + 0 * 256) & 31) * 4;
    const int lkk1 = (tid + 1 * 256) >> 5, lc41 = ((tid + 1 * 256) & 31) * 4;

    float4 pa0, pa1, pb0, pb1;
    pa0 = *(const float4*)&wt[lkk0 * 512 + o0 + lc40];
    pa1 = *(const float4*)&wt[lkk1 * 512 + o0 + lc41];
    pb0 = *(const float4*)&xb[lkk0 * 1024 + n0 + lc40];
    pb1 = *(const float4*)&xb[lkk1 * 1024 + n0 + lc41];
    *(float4*)&As[0][lkk0 * 128 + lc40] = pa0;
    *(float4*)&As[0][lkk1 * 128 + lc41] = pa1;
    *(float4*)&Bs[0][lkk0 * 128 + lc40] = pb0;
    *(float4*)&Bs[0][lkk1 * 128 + lc41] = pb1;

#pragma unroll 1
    for (int kt = 0; kt < 32; kt++) {
        __syncthreads();
        const int cur = kt & 1;
        if (kt < 31) {
            const int c0 = (kt + 1) * 16;
            pa0 = *(const float4*)&wt[(c0 + lkk0) * 512 + o0 + lc40];
            pa1 = *(const float4*)&wt[(c0 + lkk1) * 512 + o0 + lc41];
            pb0 = *(const float4*)&xb[(c0 + lkk0) * 1024 + n0 + lc40];
            pb1 = *(const float4*)&xb[(c0 + lkk1) * 1024 + n0 + lc41];
        }
#pragma unroll 8
        for (int kk = 0; kk < 16; kk++) {
            float4 a0 = *(float4*)&As[cur][kk * 128 + ty * 4];
            float4 a1 = *(float4*)&As[cur][kk * 128 + 64 + ty * 4];
            float4 b0 = *(float4*)&Bs[cur][kk * 128 + tx * 4];
            float4 b1 = *(float4*)&Bs[cur][kk * 128 + 64 + tx * 4];
            float av[8] = {a0.x, a0.y, a0.z, a0.w, a1.x, a1.y, a1.z, a1.w};
            float bv[8] = {b0.x, b0.y, b0.z, b0.w, b1.x, b1.y, b1.z, b1.w};
#pragma unroll
            for (int r = 0; r < 8; r++)
#pragma unroll
                for (int c = 0; c < 8; c++) acc[r][c] += av[r] * bv[c];
        }
        if (kt < 31) {
            const int nxt = cur ^ 1;
            *(float4*)&As[nxt][lkk0 * 128 + lc40] = pa0;
            *(float4*)&As[nxt][lkk1 * 128 + lc41] = pa1;
            *(float4*)&Bs[nxt][lkk0 * 128 + lc40] = pb0;
            *(float4*)&Bs[nxt][lkk1 * 128 + lc41] = pb1;
        }
    }

#pragma unroll
    for (int r = 0; r < 8; r++) {
        const int o = o0 + ((r < 4) ? (ty * 4 + r) : (64 + ty * 4 + r - 4));
        const float bb = bo[o];
        float* p = out + ((size_t)b * 512 + o) * 1024 + n0;
        *(float4*)&p[tx * 4] = make_float4(acc[r][0] + bb, acc[r][1] + bb,
                                           acc[r][2] + bb, acc[r][3] + bb);
        *(float4*)&p[64 + tx * 4] = make_float4(acc[r][4] + bb, acc[r][5] + bb,
                                                acc[r][6] + bb, acc[r][7] + bb);
    }
}

// ---------------------------------------------------------------------------
// Launch
// ---------------------------------------------------------------------------
extern "C" void kernel_launch(void* const* d_in, const int* in_sizes, int n_in,
                              void* d_out, int out_size)
{
    (void)in_sizes; (void)n_in; (void)out_size;
    const float* x     = (const float*)d_in[0];
    const float* w_q   = (const float*)d_in[1];
    const float* w_k   = (const float*)d_in[2];
    const float* w_v   = (const float*)d_in[3];
    const float* w_o   = (const float*)d_in[4];
    const float* b_o   = (const float*)d_in[5];
    const float* rel_h = (const float*)d_in[6];
    const float* rel_w = (const float*)d_in[7];
    float* out = (float*)d_out;

    cudaFuncSetAttribute(flash_kernel,
                         cudaFuncAttributeMaxDynamicSharedMemorySize,
                         FL_SMEM_BYTES);

    transpose_w_kernel<<<dim3(16, 16, 4), 256>>>(w_q, w_k, w_v, w_o);
    qkv_kernel<<<dim3(8, 4, 48), 256>>>(x);
    transpose_v_kernel<<<dim3(16, 128), 256>>>();
    flash_kernel<<<dim3(16, 128), 256, FL_SMEM_BYTES>>>(rel_h, rel_w);
    out_proj_kernel<<<dim3(8, 4, 16), 256>>>(b_o, out);
}

// round 14
// speedup vs baseline: 1.1072x; 1.1072x over previous
#include <cuda_runtime.h>

// ---------------------------------------------------------------------------
// BottleNeck MHSA: B=16, C=512, H=W=32 (N=1024), NH=8, DK=64.
// fp32 with packed fma.rn.f32x2 (FFMA2) in all GEMM inner loops:
// scalar FFMA-3reg is rt=2 (64 FMA/cyc/SM ceiling); FFMA2 doubles it.
// ---------------------------------------------------------------------------

#define Bsz 16
#define Cch 512
#define NPIX 1024
#define NHh 8
#define DKd 64
#define BH 128

typedef unsigned long long ull;

__device__ __forceinline__ ull dupf(float x) {
    ull d;
    asm("mov.b64 %0, {%1, %1};" : "=l"(d) : "r"(__float_as_uint(x)));
    return d;
}
__device__ __forceinline__ void ffma2(ull& d, ull a, ull b) {
    asm("fma.rn.f32x2 %0, %1, %2, %3;" : "=l"(d) : "l"(a), "l"(b), "l"(d));
}
__device__ __forceinline__ void fmul2(ull& d, ull a) {
    asm("mul.rn.f32x2 %0, %1, %2;" : "=l"(d) : "l"(d), "l"(a));
}
__device__ __forceinline__ float2 unpk(ull v) {
    unsigned lo, hi;
    asm("mov.b64 {%0, %1}, %2;" : "=r"(lo), "=r"(hi) : "l"(v));
    return make_float2(__uint_as_float(lo), __uint_as_float(hi));
}

__device__ float g_wt[4 * 512 * 512];        // transposed weights (c, o) x {q,k,v,o}
__device__ float g_q [BH * DKd * NPIX];      // (bh, dk, n)
__device__ float g_k [BH * DKd * NPIX];      // (bh, dk, n)
__device__ float g_vt[BH * DKd * NPIX];      // (bh, dk, n)  pre-transpose
__device__ float g_v [BH * NPIX * DKd];      // (bh, n, dk)
__device__ float g_o [Bsz * Cch * NPIX];     // (b, c=nh*64+d, n)

// ---------------------------------------------------------------------------
// Kernel 0: transpose the four 512x512 weight matrices into (c, o) layout.
// ---------------------------------------------------------------------------
__global__ __launch_bounds__(256) void transpose_w_kernel(
    const float* __restrict__ wq, const float* __restrict__ wk,
    const float* __restrict__ wv, const float* __restrict__ wo)
{
    __shared__ float t[32][33];
    const float* w = (blockIdx.z == 0) ? wq : (blockIdx.z == 1) ? wk
                   : (blockIdx.z == 2) ? wv : wo;
    float* wt = g_wt + (size_t)blockIdx.z * 512 * 512;
    const int c0 = blockIdx.x * 32, o0 = blockIdx.y * 32;
    const int tx = threadIdx.x & 31, ty = threadIdx.x >> 5;
#pragma unroll
    for (int i = 0; i < 4; i++)
        t[ty + i * 8][tx] = w[(o0 + ty + i * 8) * 512 + c0 + tx];
    __syncthreads();
#pragma unroll
    for (int i = 0; i < 4; i++)
        wt[(c0 + ty + i * 8) * 512 + o0 + tx] = t[tx][ty + i * 8];
}

// ---------------------------------------------------------------------------
// Kernel 1: QKV projection. 128x128 tile, K-tile 16, 8x8 micro via FFMA2.
// ---------------------------------------------------------------------------
__global__ __launch_bounds__(256, 2) void qkv_kernel(const float* __restrict__ x)
{
    const int nt = blockIdx.x, mt = blockIdx.y;
    const int z = blockIdx.z;
    const int b = z / 3, wsel = z - 3 * b;
    const int o0 = mt * 128, n0 = nt * 128;
    const float* wt = g_wt + (size_t)wsel * 512 * 512;
    const float* xb = x + (size_t)b * Cch * NPIX;

    __shared__ __align__(16) float As[2][16 * 128];
    __shared__ __align__(16) float Bs[2][16 * 128];

    const int tid = threadIdx.x;
    const int tx = tid & 15, ty = tid >> 4;

    ull acc2[8][4];
#pragma unroll
    for (int r = 0; r < 8; r++)
#pragma unroll
        for (int c = 0; c < 4; c++) acc2[r][c] = 0ull;

    const int lkk0 = (tid + 0 * 256) >> 5, lc40 = ((tid + 0 * 256) & 31) * 4;
    const int lkk1 = (tid + 1 * 256) >> 5, lc41 = ((tid + 1 * 256) & 31) * 4;

    float4 pa0, pa1, pb0, pb1;
    pa0 = *(const float4*)&wt[lkk0 * 512 + o0 + lc40];
    pa1 = *(const float4*)&wt[lkk1 * 512 + o0 + lc41];
    pb0 = *(const float4*)&xb[lkk0 * 1024 + n0 + lc40];
    pb1 = *(const float4*)&xb[lkk1 * 1024 + n0 + lc41];
    *(float4*)&As[0][lkk0 * 128 + lc40] = pa0;
    *(float4*)&As[0][lkk1 * 128 + lc41] = pa1;
    *(float4*)&Bs[0][lkk0 * 128 + lc40] = pb0;
    *(float4*)&Bs[0][lkk1 * 128 + lc41] = pb1;

#pragma unroll 1
    for (int kt = 0; kt < 32; kt++) {
        __syncthreads();
        const int cur = kt & 1;
        if (kt < 31) {
            const int c0 = (kt + 1) * 16;
            pa0 = *(const float4*)&wt[(c0 + lkk0) * 512 + o0 + lc40];
            pa1 = *(const float4*)&wt[(c0 + lkk1) * 512 + o0 + lc41];
            pb0 = *(const float4*)&xb[(c0 + lkk0) * 1024 + n0 + lc40];
            pb1 = *(const float4*)&xb[(c0 + lkk1) * 1024 + n0 + lc41];
        }
#pragma unroll 8
        for (int kk = 0; kk < 16; kk++) {
            float4 a0 = *(float4*)&As[cur][kk * 128 + ty * 4];
            float4 a1 = *(float4*)&As[cur][kk * 128 + 64 + ty * 4];
            ulonglong2 b0 = *(ulonglong2*)&Bs[cur][kk * 128 + tx * 4];
            ulonglong2 b1 = *(ulonglong2*)&Bs[cur][kk * 128 + 64 + tx * 4];
            ull bv[4] = {b0.x, b0.y, b1.x, b1.y};
            ull ad[8] = {dupf(a0.x), dupf(a0.y), dupf(a0.z), dupf(a0.w),
                         dupf(a1.x), dupf(a1.y), dupf(a1.z), dupf(a1.w)};
#pragma unroll
            for (int r = 0; r < 8; r++)
#pragma unroll
                for (int c = 0; c < 4; c++) ffma2(acc2[r][c], ad[r], bv[c]);
        }
        if (kt < 31) {
            const int nxt = cur ^ 1;
            *(float4*)&As[nxt][lkk0 * 128 + lc40] = pa0;
            *(float4*)&As[nxt][lkk1 * 128 + lc41] = pa1;
            *(float4*)&Bs[nxt][lkk0 * 128 + lc40] = pb0;
            *(float4*)&Bs[nxt][lkk1 * 128 + lc41] = pb1;
        }
    }

    float* dst = (wsel == 0) ? g_q : (wsel == 1) ? g_k : g_vt;
#pragma unroll
    for (int r = 0; r < 8; r++) {
        const int o = o0 + ((r < 4) ? (ty * 4 + r) : (64 + ty * 4 + r - 4));
        const int nh = o & 7, dk = o >> 3;
        const int bh = b * 8 + nh;
        float* p = dst + ((size_t)bh * 64 + dk) * 1024 + n0;
        float2 e0 = unpk(acc2[r][0]), e1 = unpk(acc2[r][1]);
        float2 e2 = unpk(acc2[r][2]), e3 = unpk(acc2[r][3]);
        *(float4*)&p[tx * 4]      = make_float4(e0.x, e0.y, e1.x, e1.y);
        *(float4*)&p[64 + tx * 4] = make_float4(e2.x, e2.y, e3.x, e3.y);
    }
}

// ---------------------------------------------------------------------------
// Kernel 2: transpose V (bh, dk, n) -> (bh, n, dk).
// ---------------------------------------------------------------------------
__global__ __launch_bounds__(256) void transpose_v_kernel()
{
    __shared__ float t[64][65];
    const int bh = blockIdx.y, n0 = blockIdx.x * 64;
    const float* src = g_vt + (size_t)bh * 64 * 1024;
    float* dst = g_v + (size_t)bh * 1024 * 64;
#pragma unroll
    for (int i = 0; i < 16; i++) {
        int id = threadIdx.x + i * 256;
        int d = id >> 6, n = id & 63;
        t[d][n] = src[d * 1024 + n0 + n];
    }
    __syncthreads();
#pragma unroll
    for (int i = 0; i < 16; i++) {
        int id = threadIdx.x + i * 256;
        int n = id >> 6, d = id & 63;
        dst[(size_t)(n0 + n) * 64 + d] = t[d][n];
    }
}

// ---------------------------------------------------------------------------
// Kernel 3: flash attention. Q-tile 64, K-tile 128, 4x8 micro via FFMA2.
// ---------------------------------------------------------------------------
#define FL_QS  0
#define FL_KV  (FL_QS + 64 * 68)
#define FL_PS  (FL_KV + 8192)
#define FL_RBH (FL_PS + 64 * 132)
#define FL_RBW (FL_RBH + 64 * 33)
#define FL_TOT_FLOATS (FL_RBW + 64 * 36)
#define FL_SMEM_BYTES (FL_TOT_FLOATS * 4)

__global__ __launch_bounds__(256, 2) void flash_kernel(
    const float* __restrict__ rel_h, const float* __restrict__ rel_w)
{
    extern __shared__ __align__(16) float sm[];
    float* Qs  = sm + FL_QS;
    float* KV  = sm + FL_KV;
    float* Ps  = sm + FL_PS;
    float* RBh = sm + FL_RBH;
    float* RBw = sm + FL_RBW;

    const int qt = blockIdx.x;     // 0..15
    const int bh = blockIdx.y;     // 0..127
    const int b = bh >> 3, nh = bh & 7;
    const int q0 = qt * 64;
    const int tid = threadIdx.x, tx = tid & 15, ty = tid >> 4;

    const float* qg = g_q + (size_t)bh * 64 * 1024;
    const float* kg = g_k + (size_t)bh * 64 * 1024;
    const float* vg = g_v + (size_t)bh * 1024 * 64;

    // Q load (64dk x 64q), scaled by 1/8 (scales both energy and bias)
#pragma unroll
    for (int i = 0; i < 4; i++) {
        int id = tid + i * 256;
        int dk = id >> 4, c4 = (id & 15) * 4;
        float4 t = *(const float4*)&qg[dk * 1024 + q0 + c4];
        t.x *= 0.125f; t.y *= 0.125f; t.z *= 0.125f; t.w *= 0.125f;
        *(float4*)&Qs[dk * 68 + c4] = t;
    }
    __syncthreads();

    // Bias tables: RBh[p][c] = q_p.rel_h[c-xp+31], RBw[p][j] = q_p.rel_w[j-yp+31]
    {
        const int p = tid & 63;
        const int cbase = (tid >> 6) * 16;
        float myq[64];
#pragma unroll
        for (int dk = 0; dk < 64; dk++) myq[dk] = Qs[dk * 68 + p];
        const int xp = qt * 2 + (p >> 5);
        const int yp = p & 31;
#pragma unroll
        for (int j = 0; j < 16; j++) {
            const int c = cbase + j;
            const float* rr = (c < 32) ? (rel_h + (c - xp + 31) * 64)
                                       : (rel_w + ((c - 32) - yp + 31) * 64);
            float s = 0.f;
#pragma unroll
            for (int k4 = 0; k4 < 16; k4++) {
                float4 r4 = *(const float4*)&rr[k4 * 4];
                s += myq[k4 * 4 + 0] * r4.x + myq[k4 * 4 + 1] * r4.y
                   + myq[k4 * 4 + 2] * r4.z + myq[k4 * 4 + 3] * r4.w;
            }
            if (c < 32) RBh[p * 33 + c] = s;
            else        RBw[p * 36 + (c - 32)] = s;
        }
    }

    float m_[4], l_[4];
    ull oa2[4][2];
#pragma unroll
    for (int r = 0; r < 4; r++) {
        m_[r] = -1e30f; l_[r] = 0.f;
        oa2[r][0] = 0ull; oa2[r][1] = 0ull;
    }

    const int j0 = (tx * 4) & 31;

#pragma unroll 1
    for (int kt = 0; kt < 8; kt++) {
        __syncthreads();
        // Load K tile (dk-major) into KV
#pragma unroll
        for (int i = 0; i < 8; i++) {
            int id = tid + i * 256;
            int r_ = id >> 5, c4 = (id & 31) * 4;
            *(float4*)&KV[r_ * 128 + c4] =
                *(const float4*)&kg[r_ * 1024 + kt * 128 + c4];
        }
        __syncthreads();

        // S = Q^T K : 4q x 8k per thread, packed over key pairs
        ull s2[4][4];
#pragma unroll
        for (int r = 0; r < 4; r++)
#pragma unroll
            for (int c = 0; c < 4; c++) s2[r][c] = 0ull;
#pragma unroll 8
        for (int kk = 0; kk < 64; kk++) {
            float4 a4 = *(float4*)&Qs[kk * 68 + ty * 4];
            ulonglong2 b0 = *(ulonglong2*)&KV[kk * 128 + tx * 4];
            ulonglong2 b1 = *(ulonglong2*)&KV[kk * 128 + 64 + tx * 4];
            ull bv[4] = {b0.x, b0.y, b1.x, b1.y};
            ull ad[4] = {dupf(a4.x), dupf(a4.y), dupf(a4.z), dupf(a4.w)};
#pragma unroll
            for (int r = 0; r < 4; r++)
#pragma unroll
                for (int c = 0; c < 4; c++) ffma2(s2[r][c], ad[r], bv[c]);
        }

        // unpack S
        float s[4][8];
#pragma unroll
        for (int r = 0; r < 4; r++) {
            float2 e0 = unpk(s2[r][0]), e1 = unpk(s2[r][1]);
            float2 e2 = unpk(s2[r][2]), e3 = unpk(s2[r][3]);
            s[r][0] = e0.x; s[r][1] = e0.y; s[r][2] = e1.x; s[r][3] = e1.y;
            s[r][4] = e2.x; s[r][5] = e2.y; s[r][6] = e3.x; s[r][7] = e3.y;
        }

        // bias add
        const int iA = kt * 4 + (tx >> 3);
        const int iB = iA + 2;
#pragma unroll
        for (int r = 0; r < 4; r++) {
            const int row = ty * 4 + r;
            float hA = RBh[row * 33 + iA];
            float hB = RBh[row * 33 + iB];
            float4 w4 = *(float4*)&RBw[row * 36 + j0];
            float wv[4] = {w4.x, w4.y, w4.z, w4.w};
#pragma unroll
            for (int c = 0; c < 4; c++) s[r][c]     += hA + wv[c];
#pragma unroll
            for (int c = 0; c < 4; c++) s[r][4 + c] += hB + wv[c];
        }

        // online softmax
#pragma unroll
        for (int r = 0; r < 4; r++) {
            float tm = s[r][0];
#pragma unroll
            for (int c = 1; c < 8; c++) tm = fmaxf(tm, s[r][c]);
#pragma unroll
            for (int o = 8; o >= 1; o >>= 1)
                tm = fmaxf(tm, __shfl_xor_sync(0xffffffffu, tm, o));
            float mnew = fmaxf(m_[r], tm);
            float sc = __expf(m_[r] - mnew);
            float rs = 0.f;
#pragma unroll
            for (int c = 0; c < 8; c++) { s[r][c] = __expf(s[r][c] - mnew); rs += s[r][c]; }
#pragma unroll
            for (int o = 8; o >= 1; o >>= 1)
                rs += __shfl_xor_sync(0xffffffffu, rs, o);
            l_[r] = l_[r] * sc + rs;
            m_[r] = mnew;
            ull sc2 = dupf(sc);
            fmul2(oa2[r][0], sc2);
            fmul2(oa2[r][1], sc2);
        }

        // store P (q-major)
#pragma unroll
        for (int r = 0; r < 4; r++) {
            const int row = ty * 4 + r;
            *(float4*)&Ps[row * 132 + tx * 4] =
                make_float4(s[r][0], s[r][1], s[r][2], s[r][3]);
            *(float4*)&Ps[row * 132 + 64 + tx * 4] =
                make_float4(s[r][4], s[r][5], s[r][6], s[r][7]);
        }
        __syncthreads();              // K reads done -> overwrite with V

        // Load V tile (key-major) into KV
#pragma unroll
        for (int i = 0; i < 8; i++) {
            int id = tid + i * 256;
            int r_ = id >> 4, c4 = (id & 15) * 4;
            *(float4*)&KV[r_ * 64 + c4] =
                *(const float4*)&vg[(size_t)(kt * 128 + r_) * 64 + c4];
        }
        __syncthreads();

        // O += P @ V : packed over d pairs
#pragma unroll 4
        for (int c4 = 0; c4 < 32; c4++) {
            ulonglong2 v0 = *(ulonglong2*)&KV[(c4 * 4 + 0) * 64 + tx * 4];
            ulonglong2 v1 = *(ulonglong2*)&KV[(c4 * 4 + 1) * 64 + tx * 4];
            ulonglong2 v2 = *(ulonglong2*)&KV[(c4 * 4 + 2) * 64 + tx * 4];
            ulonglong2 v3 = *(ulonglong2*)&KV[(c4 * 4 + 3) * 64 + tx * 4];
#pragma unroll
            for (int r = 0; r < 4; r++) {
                float4 pf = *(float4*)&Ps[(ty * 4 + r) * 132 + c4 * 4];
                ull p0 = dupf(pf.x), p1 = dupf(pf.y), p2 = dupf(pf.z), p3 = dupf(pf.w);
                ffma2(oa2[r][0], p0, v0.x); ffma2(oa2[r][1], p0, v0.y);
                ffma2(oa2[r][0], p1, v1.x); ffma2(oa2[r][1], p1, v1.y);
                ffma2(oa2[r][0], p2, v2.x); ffma2(oa2[r][1], p2, v2.y);
                ffma2(oa2[r][0], p3, v3.x); ffma2(oa2[r][1], p3, v3.y);
            }
        }
    }

    // epilogue: normalize, stage via Ps, write coalesced (d-major rows)
#pragma unroll
    for (int r = 0; r < 4; r++) {
        float il = 1.f / l_[r];
        float2 e0 = unpk(oa2[r][0]), e1 = unpk(oa2[r][1]);
        *(float4*)&Ps[(ty * 4 + r) * 132 + tx * 4] =
            make_float4(e0.x * il, e0.y * il, e1.x * il, e1.y * il);
    }
    __syncthreads();
    float* og = g_o + ((size_t)b * 512 + nh * 64) * 1024 + q0;
#pragma unroll
    for (int i = 0; i < 16; i++) {
        int id = tid + i * 256;
        int q = id & 63, d = id >> 6;
        og[d * 1024 + q] = Ps[q * 132 + d];
    }
}

// ---------------------------------------------------------------------------
// Kernel 4: output projection + bias (FFMA2).
// ---------------------------------------------------------------------------
__global__ __launch_bounds__(256, 2) void out_proj_kernel(
    const float* __restrict__ bo, float* __restrict__ out)
{
    const int nt = blockIdx.x, mt = blockIdx.y, b = blockIdx.z;
    const int o0 = mt * 128, n0 = nt * 128;
    const float* wt = g_wt + (size_t)3 * 512 * 512;
    const float* xb = g_o + (size_t)b * Cch * NPIX;

    __shared__ __align__(16) float As[2][16 * 128];
    __shared__ __align__(16) float Bs[2][16 * 128];

    const int tid = threadIdx.x;
    const int tx = tid & 15, ty = tid >> 4;

    ull acc2[8][4];
#pragma unroll
    for (int r = 0; r < 8; r++)
#pragma unroll
        for (int c = 0; c < 4; c++) acc2[r][c] = 0ull;

    const int lkk0 = (tid + 0 * 256) >> 5, lc40 = ((tid + 0 * 256) & 31) * 4;
    const int lkk1 = (tid + 1 * 256) >> 5, lc41 = ((tid + 1 * 256) & 31) * 4;

    float4 pa0, pa1, pb0, pb1;
    pa0 = *(const float4*)&wt[lkk0 * 512 + o0 + lc40];
    pa1 = *(const float4*)&wt[lkk1 * 512 + o0 + lc41];
    pb0 = *(const float4*)&xb[lkk0 * 1024 + n0 + lc40];
    pb1 = *(const float4*)&xb[lkk1 * 1024 + n0 + lc41];
    *(float4*)&As[0][lkk0 * 128 + lc40] = pa0;
    *(float4*)&As[0][lkk1 * 128 + lc41] = pa1;
    *(float4*)&Bs[0][lkk0 * 128 + lc40] = pb0;
    *(float4*)&Bs[0][lkk1 * 128 + lc41] = pb1;

#pragma unroll 1
    for (int kt = 0; kt < 32; kt++) {
        __syncthreads();
        const int cur = kt & 1;
        if (kt < 31) {
            const int c0 = (kt + 1) * 16;
            pa0 = *(const float4*)&wt[(c0 + lkk0) * 512 + o0 + lc40];
            pa1 = *(const float4*)&wt[(c0 + lkk1) * 512 + o0 + lc41];
            pb0 = *(const float4*)&xb[(c0 + lkk0) * 1024 + n0 + lc40];
            pb1 = *(const float4*)&xb[(c0 + lkk1) * 1024 + n0 + lc41];
        }
#pragma unroll 8
        for (int kk = 0; kk < 16; kk++) {
            float4 a0 = *(float4*)&As[cur][kk * 128 + ty * 4];
            float4 a1 = *(float4*)&As[cur][kk * 128 + 64 + ty * 4];
            ulonglong2 b0 = *(ulonglong2*)&Bs[cur][kk * 128 + tx * 4];
            ulonglong2 b1 = *(ulonglong2*)&Bs[cur][kk * 128 + 64 + tx * 4];
            ull bv[4] = {b0.x, b0.y, b1.x, b1.y};
            ull ad[8] = {dupf(a0.x), dupf(a0.y), dupf(a0.z), dupf(a0.w),
                         dupf(a1.x), dupf(a1.y), dupf(a1.z), dupf(a1.w)};
#pragma unroll
            for (int r = 0; r < 8; r++)
#pragma unroll
                for (int c = 0; c < 4; c++) ffma2(acc2[r][c], ad[r], bv[c]);
        }
        if (kt < 31) {
            const int nxt = cur ^ 1;
            *(float4*)&As[nxt][lkk0 * 128 + lc40] = pa0;
            *(float4*)&As[nxt][lkk1 * 128 + lc41] = pa1;
            *(float4*)&Bs[nxt][lkk0 * 128 + lc40] = pb0;
            *(float4*)&Bs[nxt][lkk1 * 128 + lc41] = pb1;
        }
    }

#pragma unroll
    for (int r = 0; r < 8; r++) {
        const int o = o0 + ((r < 4) ? (ty * 4 + r) : (64 + ty * 4 + r - 4));
        const float bb = bo[o];
        float* p = out + ((size_t)b * 512 + o) * 1024 + n0;
        float2 e0 = unpk(acc2[r][0]), e1 = unpk(acc2[r][1]);
        float2 e2 = unpk(acc2[r][2]), e3 = unpk(acc2[r][3]);
        *(float4*)&p[tx * 4] = make_float4(e0.x + bb, e0.y + bb, e1.x + bb, e1.y + bb);
        *(float4*)&p[64 + tx * 4] = make_float4(e2.x + bb, e2.y + bb, e3.x + bb, e3.y + bb);
    }
}

// ---------------------------------------------------------------------------
// Launch
// ---------------------------------------------------------------------------
extern "C" void kernel_launch(void* const* d_in, const int* in_sizes, int n_in,
                              void* d_out, int out_size)
{
    (void)in_sizes; (void)n_in; (void)out_size;
    const float* x     = (const float*)d_in[0];
    const float* w_q   = (const float*)d_in[1];
    const float* w_k   = (const float*)d_in[2];
    const float* w_v   = (const float*)d_in[3];
    const float* w_o   = (const float*)d_in[4];
    const float* b_o   = (const float*)d_in[5];
    const float* rel_h = (const float*)d_in[6];
    const float* rel_w = (const float*)d_in[7];
    float* out = (float*)d_out;

    cudaFuncSetAttribute(flash_kernel,
                         cudaFuncAttributeMaxDynamicSharedMemorySize,
                         FL_SMEM_BYTES);

    transpose_w_kernel<<<dim3(16, 16, 4), 256>>>(w_q, w_k, w_v, w_o);
    qkv_kernel<<<dim3(8, 4, 48), 256>>>(x);
    transpose_v_kernel<<<dim3(16, 128), 256>>>();
    flash_kernel<<<dim3(16, 128), 256, FL_SMEM_BYTES>>>(rel_h, rel_w);
    out_proj_kernel<<<dim3(8, 4, 16), 256>>>(b_o, out);
}

// round 15
// speedup vs baseline: 1.1096x; 1.0022x over previous
#include <cuda_runtime.h>

// ---------------------------------------------------------------------------
// BottleNeck MHSA: B=16, C=512, H=W=32 (N=1024), NH=8, DK=64.
// fp32 with packed fma.rn.f32x2 (FFMA2) in all GEMM inner loops:
// scalar FFMA-3reg is rt=2 (64 FMA/cyc/SM ceiling); FFMA2 doubles it.
// ---------------------------------------------------------------------------

#define Bsz 16
#define Cch 512
#define NPIX 1024
#define NHh 8
#define DKd 64
#define BH 128

typedef unsigned long long ull;

__device__ __forceinline__ ull dupf(float x) {
    ull d;
    asm("mov.b64 %0, {%1, %1};" : "=l"(d) : "r"(__float_as_uint(x)));
    return d;
}
__device__ __forceinline__ void ffma2(ull& d, ull a, ull b) {
    asm("fma.rn.f32x2 %0, %1, %2, %3;" : "=l"(d) : "l"(a), "l"(b), "l"(d));
}
__device__ __forceinline__ void fmul2(ull& d, ull a) {
    asm("mul.rn.f32x2 %0, %1, %2;" : "=l"(d) : "l"(d), "l"(a));
}
__device__ __forceinline__ float2 unpk(ull v) {
    unsigned lo, hi;
    asm("mov.b64 {%0, %1}, %2;" : "=r"(lo), "=r"(hi) : "l"(v));
    return make_float2(__uint_as_float(lo), __uint_as_float(hi));
}

__device__ float g_wt[4 * 512 * 512];        // transposed weights (c, o) x {q,k,v,o}
__device__ float g_q [BH * DKd * NPIX];      // (bh, dk, n)
__device__ float g_k [BH * DKd * NPIX];      // (bh, dk, n)
__device__ float g_vt[BH * DKd * NPIX];      // (bh, dk, n)  pre-transpose
__device__ float g_v [BH * NPIX * DKd];      // (bh, n, dk)
__device__ float g_o [Bsz * Cch * NPIX];     // (b, c=nh*64+d, n)

// ---------------------------------------------------------------------------
// Kernel 0: transpose the four 512x512 weight matrices into (c, o) layout.
// ---------------------------------------------------------------------------
__global__ __launch_bounds__(256) void transpose_w_kernel(
    const float* __restrict__ wq, const float* __restrict__ wk,
    const float* __restrict__ wv, const float* __restrict__ wo)
{
    __shared__ float t[32][33];
    const float* w = (blockIdx.z == 0) ? wq : (blockIdx.z == 1) ? wk
                   : (blockIdx.z == 2) ? wv : wo;
    float* wt = g_wt + (size_t)blockIdx.z * 512 * 512;
    const int c0 = blockIdx.x * 32, o0 = blockIdx.y * 32;
    const int tx = threadIdx.x & 31, ty = threadIdx.x >> 5;
#pragma unroll
    for (int i = 0; i < 4; i++)
        t[ty + i * 8][tx] = w[(o0 + ty + i * 8) * 512 + c0 + tx];
    __syncthreads();
#pragma unroll
    for (int i = 0; i < 4; i++)
        wt[(c0 + ty + i * 8) * 512 + o0 + tx] = t[tx][ty + i * 8];
}

// ---------------------------------------------------------------------------
// Kernel 1: QKV projection. 128x128 tile, K-tile 16, 8x8 micro via FFMA2.
// ---------------------------------------------------------------------------
__global__ __launch_bounds__(256, 2) void qkv_kernel(const float* __restrict__ x)
{
    const int nt = blockIdx.x, mt = blockIdx.y;
    const int z = blockIdx.z;
    const int b = z / 3, wsel = z - 3 * b;
    const int o0 = mt * 128, n0 = nt * 128;
    const float* wt = g_wt + (size_t)wsel * 512 * 512;
    const float* xb = x + (size_t)b * Cch * NPIX;

    __shared__ __align__(16) float As[2][16 * 128];
    __shared__ __align__(16) float Bs[2][16 * 128];

    const int tid = threadIdx.x;
    const int tx = tid & 15, ty = tid >> 4;

    ull acc2[8][4];
#pragma unroll
    for (int r = 0; r < 8; r++)
#pragma unroll
        for (int c = 0; c < 4; c++) acc2[r][c] = 0ull;

    const int lkk0 = (tid + 0 * 256) >> 5, lc40 = ((tid + 0 * 256) & 31) * 4;
    const int lkk1 = (tid + 1 * 256) >> 5, lc41 = ((tid + 1 * 256) & 31) * 4;

    float4 pa0, pa1, pb0, pb1;
    pa0 = *(const float4*)&wt[lkk0 * 512 + o0 + lc40];
    pa1 = *(const float4*)&wt[lkk1 * 512 + o0 + lc41];
    pb0 = *(const float4*)&xb[lkk0 * 1024 + n0 + lc40];
    pb1 = *(const float4*)&xb[lkk1 * 1024 + n0 + lc41];
    *(float4*)&As[0][lkk0 * 128 + lc40] = pa0;
    *(float4*)&As[0][lkk1 * 128 + lc41] = pa1;
    *(float4*)&Bs[0][lkk0 * 128 + lc40] = pb0;
    *(float4*)&Bs[0][lkk1 * 128 + lc41] = pb1;

#pragma unroll 1
    for (int kt = 0; kt < 32; kt++) {
        __syncthreads();
        const int cur = kt & 1;
        if (kt < 31) {
            const int c0 = (kt + 1) * 16;
            pa0 = *(const float4*)&wt[(c0 + lkk0) * 512 + o0 + lc40];
            pa1 = *(const float4*)&wt[(c0 + lkk1) * 512 + o0 + lc41];
            pb0 = *(const float4*)&xb[(c0 + lkk0) * 1024 + n0 + lc40];
            pb1 = *(const float4*)&xb[(c0 + lkk1) * 1024 + n0 + lc41];
        }
#pragma unroll 8
        for (int kk = 0; kk < 16; kk++) {
            float4 a0 = *(float4*)&As[cur][kk * 128 + ty * 4];
            float4 a1 = *(float4*)&As[cur][kk * 128 + 64 + ty * 4];
            ulonglong2 b0 = *(ulonglong2*)&Bs[cur][kk * 128 + tx * 4];
            ulonglong2 b1 = *(ulonglong2*)&Bs[cur][kk * 128 + 64 + tx * 4];
            ull bv[4] = {b0.x, b0.y, b1.x, b1.y};
            ull ad[8] = {dupf(a0.x), dupf(a0.y), dupf(a0.z), dupf(a0.w),
                         dupf(a1.x), dupf(a1.y), dupf(a1.z), dupf(a1.w)};
#pragma unroll
            for (int r = 0; r < 8; r++)
#pragma unroll
                for (int c = 0; c < 4; c++) ffma2(acc2[r][c], ad[r], bv[c]);
        }
        if (kt < 31) {
            const int nxt = cur ^ 1;
            *(float4*)&As[nxt][lkk0 * 128 + lc40] = pa0;
            *(float4*)&As[nxt][lkk1 * 128 + lc41] = pa1;
            *(float4*)&Bs[nxt][lkk0 * 128 + lc40] = pb0;
            *(float4*)&Bs[nxt][lkk1 * 128 + lc41] = pb1;
        }
    }

    float* dst = (wsel == 0) ? g_q : (wsel == 1) ? g_k : g_vt;
#pragma unroll
    for (int r = 0; r < 8; r++) {
        const int o = o0 + ((r < 4) ? (ty * 4 + r) : (64 + ty * 4 + r - 4));
        const int nh = o & 7, dk = o >> 3;
        const int bh = b * 8 + nh;
        float* p = dst + ((size_t)bh * 64 + dk) * 1024 + n0;
        float2 e0 = unpk(acc2[r][0]), e1 = unpk(acc2[r][1]);
        float2 e2 = unpk(acc2[r][2]), e3 = unpk(acc2[r][3]);
        *(float4*)&p[tx * 4]      = make_float4(e0.x, e0.y, e1.x, e1.y);
        *(float4*)&p[64 + tx * 4] = make_float4(e2.x, e2.y, e3.x, e3.y);
    }
}

// ---------------------------------------------------------------------------
// Kernel 2: transpose V (bh, dk, n) -> (bh, n, dk).
// ---------------------------------------------------------------------------
__global__ __launch_bounds__(256) void transpose_v_kernel()
{
    __shared__ float t[64][65];
    const int bh = blockIdx.y, n0 = blockIdx.x * 64;
    const float* src = g_vt + (size_t)bh * 64 * 1024;
    float* dst = g_v + (size_t)bh * 1024 * 64;
#pragma unroll
    for (int i = 0; i < 16; i++) {
        int id = threadIdx.x + i * 256;
        int d = id >> 6, n = id & 63;
        t[d][n] = src[d * 1024 + n0 + n];
    }
    __syncthreads();
#pragma unroll
    for (int i = 0; i < 16; i++) {
        int id = threadIdx.x + i * 256;
        int n = id >> 6, d = id & 63;
        dst[(size_t)(n0 + n) * 64 + d] = t[d][n];
    }
}

// ---------------------------------------------------------------------------
// Kernel 3: flash attention. Q-tile 64, K-tile 128, 4x8 micro via FFMA2.
// ---------------------------------------------------------------------------
#define FL_QS  0
#define FL_KV  (FL_QS + 64 * 68)
#define FL_PS  (FL_KV + 8192)
#define FL_RBH (FL_PS + 64 * 132)
#define FL_RBW (FL_RBH + 64 * 33)
#define FL_TOT_FLOATS (FL_RBW + 64 * 36)
#define FL_SMEM_BYTES (FL_TOT_FLOATS * 4)

__global__ __launch_bounds__(256, 2) void flash_kernel(
    const float* __restrict__ rel_h, const float* __restrict__ rel_w)
{
    extern __shared__ __align__(16) float sm[];
    float* Qs  = sm + FL_QS;
    float* KV  = sm + FL_KV;
    float* Ps  = sm + FL_PS;
    float* RBh = sm + FL_RBH;
    float* RBw = sm + FL_RBW;

    const int qt = blockIdx.x;     // 0..15
    const int bh = blockIdx.y;     // 0..127
    const int b = bh >> 3, nh = bh & 7;
    const int q0 = qt * 64;
    const int tid = threadIdx.x, tx = tid & 15, ty = tid >> 4;

    const float* qg = g_q + (size_t)bh * 64 * 1024;
    const float* kg = g_k + (size_t)bh * 64 * 1024;
    const float* vg = g_v + (size_t)bh * 1024 * 64;

    // Q load (64dk x 64q), scaled by 1/8 (scales both energy and bias)
#pragma unroll
    for (int i = 0; i < 4; i++) {
        int id = tid + i * 256;
        int dk = id >> 4, c4 = (id & 15) * 4;
        float4 t = *(const float4*)&qg[dk * 1024 + q0 + c4];
        t.x *= 0.125f; t.y *= 0.125f; t.z *= 0.125f; t.w *= 0.125f;
        *(float4*)&Qs[dk * 68 + c4] = t;
    }
    __syncthreads();

    // Bias tables: RBh[p][c] = q_p.rel_h[c-xp+31], RBw[p][j] = q_p.rel_w[j-yp+31]
    {
        const int p = tid & 63;
        const int cbase = (tid >> 6) * 16;
        float myq[64];
#pragma unroll
        for (int dk = 0; dk < 64; dk++) myq[dk] = Qs[dk * 68 + p];
        const int xp = qt * 2 + (p >> 5);
        const int yp = p & 31;
#pragma unroll
        for (int j = 0; j < 16; j++) {
            const int c = cbase + j;
            const float* rr = (c < 32) ? (rel_h + (c - xp + 31) * 64)
                                       : (rel_w + ((c - 32) - yp + 31) * 64);
            float s = 0.f;
#pragma unroll
            for (int k4 = 0; k4 < 16; k4++) {
                float4 r4 = *(const float4*)&rr[k4 * 4];
                s += myq[k4 * 4 + 0] * r4.x + myq[k4 * 4 + 1] * r4.y
                   + myq[k4 * 4 + 2] * r4.z + myq[k4 * 4 + 3] * r4.w;
            }
            if (c < 32) RBh[p * 33 + c] = s;
            else        RBw[p * 36 + (c - 32)] = s;
        }
    }

    float m_[4], l_[4];
    ull oa2[4][2];
#pragma unroll
    for (int r = 0; r < 4; r++) {
        m_[r] = -1e30f; l_[r] = 0.f;
        oa2[r][0] = 0ull; oa2[r][1] = 0ull;
    }

    const int j0 = (tx * 4) & 31;

#pragma unroll 1
    for (int kt = 0; kt < 8; kt++) {
        __syncthreads();
        // Load K tile (dk-major) into KV
#pragma unroll
        for (int i = 0; i < 8; i++) {
            int id = tid + i * 256;
            int r_ = id >> 5, c4 = (id & 31) * 4;
            *(float4*)&KV[r_ * 128 + c4] =
                *(const float4*)&kg[r_ * 1024 + kt * 128 + c4];
        }
        __syncthreads();

        // S = Q^T K : 4q x 8k per thread, packed over key pairs
        ull s2[4][4];
#pragma unroll
        for (int r = 0; r < 4; r++)
#pragma unroll
            for (int c = 0; c < 4; c++) s2[r][c] = 0ull;
#pragma unroll 8
        for (int kk = 0; kk < 64; kk++) {
            float4 a4 = *(float4*)&Qs[kk * 68 + ty * 4];
            ulonglong2 b0 = *(ulonglong2*)&KV[kk * 128 + tx * 4];
            ulonglong2 b1 = *(ulonglong2*)&KV[kk * 128 + 64 + tx * 4];
            ull bv[4] = {b0.x, b0.y, b1.x, b1.y};
            ull ad[4] = {dupf(a4.x), dupf(a4.y), dupf(a4.z), dupf(a4.w)};
#pragma unroll
            for (int r = 0; r < 4; r++)
#pragma unroll
                for (int c = 0; c < 4; c++) ffma2(s2[r][c], ad[r], bv[c]);
        }

        // unpack S
        float s[4][8];
#pragma unroll
        for (int r = 0; r < 4; r++) {
            float2 e0 = unpk(s2[r][0]), e1 = unpk(s2[r][1]);
            float2 e2 = unpk(s2[r][2]), e3 = unpk(s2[r][3]);
            s[r][0] = e0.x; s[r][1] = e0.y; s[r][2] = e1.x; s[r][3] = e1.y;
            s[r][4] = e2.x; s[r][5] = e2.y; s[r][6] = e3.x; s[r][7] = e3.y;
        }

        // bias add
        const int iA = kt * 4 + (tx >> 3);
        const int iB = iA + 2;
#pragma unroll
        for (int r = 0; r < 4; r++) {
            const int row = ty * 4 + r;
            float hA = RBh[row * 33 + iA];
            float hB = RBh[row * 33 + iB];
            float4 w4 = *(float4*)&RBw[row * 36 + j0];
            float wv[4] = {w4.x, w4.y, w4.z, w4.w};
#pragma unroll
            for (int c = 0; c < 4; c++) s[r][c]     += hA + wv[c];
#pragma unroll
            for (int c = 0; c < 4; c++) s[r][4 + c] += hB + wv[c];
        }

        // online softmax
#pragma unroll
        for (int r = 0; r < 4; r++) {
            float tm = s[r][0];
#pragma unroll
            for (int c = 1; c < 8; c++) tm = fmaxf(tm, s[r][c]);
#pragma unroll
            for (int o = 8; o >= 1; o >>= 1)
                tm = fmaxf(tm, __shfl_xor_sync(0xffffffffu, tm, o));
            float mnew = fmaxf(m_[r], tm);
            float sc = __expf(m_[r] - mnew);
            float rs = 0.f;
#pragma unroll
            for (int c = 0; c < 8; c++) { s[r][c] = __expf(s[r][c] - mnew); rs += s[r][c]; }
#pragma unroll
            for (int o = 8; o >= 1; o >>= 1)
                rs += __shfl_xor_sync(0xffffffffu, rs, o);
            l_[r] = l_[r] * sc + rs;
            m_[r] = mnew;
            ull sc2 = dupf(sc);
            fmul2(oa2[r][0], sc2);
            fmul2(oa2[r][1], sc2);
        }

        // store P (q-major)
#pragma unroll
        for (int r = 0; r < 4; r++) {
            const int row = ty * 4 + r;
            *(float4*)&Ps[row * 132 + tx * 4] =
                make_float4(s[r][0], s[r][1], s[r][2], s[r][3]);
            *(float4*)&Ps[row * 132 + 64 + tx * 4] =
                make_float4(s[r][4], s[r][5], s[r][6], s[r][7]);
        }
        __syncthreads();              // K reads done -> overwrite with V

        // Load V tile (key-major) into KV
#pragma unroll
        for (int i = 0; i < 8; i++) {
            int id = tid + i * 256;
            int r_ = id >> 4, c4 = (id & 15) * 4;
            *(float4*)&KV[r_ * 64 + c4] =
                *(const float4*)&vg[(size_t)(kt * 128 + r_) * 64 + c4];
        }
        __syncthreads();

        // O += P @ V : packed over d pairs
#pragma unroll 4
        for (int c4 = 0; c4 < 32; c4++) {
            ulonglong2 v0 = *(ulonglong2*)&KV[(c4 * 4 + 0) * 64 + tx * 4];
            ulonglong2 v1 = *(ulonglong2*)&KV[(c4 * 4 + 1) * 64 + tx * 4];
            ulonglong2 v2 = *(ulonglong2*)&KV[(c4 * 4 + 2) * 64 + tx * 4];
            ulonglong2 v3 = *(ulonglong2*)&KV[(c4 * 4 + 3) * 64 + tx * 4];
#pragma unroll
            for (int r = 0; r < 4; r++) {
                float4 pf = *(float4*)&Ps[(ty * 4 + r) * 132 + c4 * 4];
                ull p0 = dupf(pf.x), p1 = dupf(pf.y), p2 = dupf(pf.z), p3 = dupf(pf.w);
                ffma2(oa2[r][0], p0, v0.x); ffma2(oa2[r][1], p0, v0.y);
                ffma2(oa2[r][0], p1, v1.x); ffma2(oa2[r][1], p1, v1.y);
                ffma2(oa2[r][0], p2, v2.x); ffma2(oa2[r][1], p2, v2.y);
                ffma2(oa2[r][0], p3, v3.x); ffma2(oa2[r][1], p3, v3.y);
            }
        }
    }

    // epilogue: normalize, stage via Ps, write coalesced (d-major rows)
#pragma unroll
    for (int r = 0; r < 4; r++) {
        float il = 1.f / l_[r];
        float2 e0 = unpk(oa2[r][0]), e1 = unpk(oa2[r][1]);
        *(float4*)&Ps[(ty * 4 + r) * 132 + tx * 4] =
            make_float4(e0.x * il, e0.y * il, e1.x * il, e1.y * il);
    }
    __syncthreads();
    float* og = g_o + ((size_t)b * 512 + nh * 64) * 1024 + q0;
#pragma unroll
    for (int i = 0; i < 16; i++) {
        int id = tid + i * 256;
        int q = id & 63, d = id >> 6;
        og[d * 1024 + q] = Ps[q * 132 + d];
    }
}

// ---------------------------------------------------------------------------
// Kernel 4: output projection + bias (FFMA2).
// ---------------------------------------------------------------------------
__global__ __launch_bounds__(256, 2) void out_proj_kernel(
    const float* __restrict__ bo, float* __restrict__ out)
{
    const int nt = blockIdx.x, mt = blockIdx.y, b = blockIdx.z;
    const int o0 = mt * 128, n0 = nt * 128;
    const float* wt = g_wt + (size_t)3 * 512 * 512;
    const float* xb = g_o + (size_t)b * Cch * NPIX;

    __shared__ __align__(16) float As[2][16 * 128];
    __shared__ __align__(16) float Bs[2][16 * 128];

    const int tid = threadIdx.x;
    const int tx = tid & 15, ty = tid >> 4;

    ull acc2[8][4];
#pragma unroll
    for (int r = 0; r < 8; r++)
#pragma unroll
        for (int c = 0; c < 4; c++) acc2[r][c] = 0ull;

    const int lkk0 = (tid + 0 * 256) >> 5, lc40 = ((tid + 0 * 256) & 31) * 4;
    const int lkk1 = (tid + 1 * 256) >> 5, lc41 = ((tid + 1 * 256) & 31) * 4;

    float4 pa0, pa1, pb0, pb1;
    pa0 = *(const float4*)&wt[lkk0 * 512 + o0 + lc40];
    pa1 = *(const float4*)&wt[lkk1 * 512 + o0 + lc41];
    pb0 = *(const float4*)&xb[lkk0 * 1024 + n0 + lc40];
    pb1 = *(const float4*)&xb[lkk1 * 1024 + n0 + lc41];
    *(float4*)&As[0][lkk0 * 128 + lc40] = pa0;
    *(float4*)&As[0][lkk1 * 128 + lc41] = pa1;
    *(float4*)&Bs[0][lkk0 * 128 + lc40] = pb0;
    *(float4*)&Bs[0][lkk1 * 128 + lc41] = pb1;

#pragma unroll 1
    for (int kt = 0; kt < 32; kt++) {
        __syncthreads();
        const int cur = kt & 1;
        if (kt < 31) {
            const int c0 = (kt + 1) * 16;
            pa0 = *(const float4*)&wt[(c0 + lkk0) * 512 + o0 + lc40];
            pa1 = *(const float4*)&wt[(c0 + lkk1) * 512 + o0 + lc41];
            pb0 = *(const float4*)&xb[(c0 + lkk0) * 1024 + n0 + lc40];
            pb1 = *(const float4*)&xb[(c0 + lkk1) * 1024 + n0 + lc41];
        }
#pragma unroll 8
        for (int kk = 0; kk < 16; kk++) {
            float4 a0 = *(float4*)&As[cur][kk * 128 + ty * 4];
            float4 a1 = *(float4*)&As[cur][kk * 128 + 64 + ty * 4];
            ulonglong2 b0 = *(ulonglong2*)&Bs[cur][kk * 128 + tx * 4];
            ulonglong2 b1 = *(ulonglong2*)&Bs[cur][kk * 128 + 64 + tx * 4];
            ull bv[4] = {b0.x, b0.y, b1.x, b1.y};
            ull ad[8] = {dupf(a0.x), dupf(a0.y), dupf(a0.z), dupf(a0.w),
                         dupf(a1.x), dupf(a1.y), dupf(a1.z), dupf(a1.w)};
#pragma unroll
            for (int r = 0; r < 8; r++)
#pragma unroll
                for (int c = 0; c < 4; c++) ffma2(acc2[r][c], ad[r], bv[c]);
        }
        if (kt < 31) {
            const int nxt = cur ^ 1;
            *(float4*)&As[nxt][lkk0 * 128 + lc40] = pa0;
            *(float4*)&As[nxt][lkk1 * 128 + lc41] = pa1;
            *(float4*)&Bs[nxt][lkk0 * 128 + lc40] = pb0;
            *(float4*)&Bs[nxt][lkk1 * 128 + lc41] = pb1;
        }
    }

#pragma unroll
    for (int r = 0; r < 8; r++) {
        const int o = o0 + ((r < 4) ? (ty * 4 + r) : (64 + ty * 4 + r - 4));
        const float bb = bo[o];
        float* p = out + ((size_t)b * 512 + o) * 1024 + n0;
        float2 e0 = unpk(acc2[r][0]), e1 = unpk(acc2[r][1]);
        float2 e2 = unpk(acc2[r][2]), e3 = unpk(acc2[r][3]);
        *(float4*)&p[tx * 4] = make_float4(e0.x + bb, e0.y + bb, e1.x + bb, e1.y + bb);
        *(float4*)&p[64 + tx * 4] = make_float4(e2.x + bb, e2.y + bb, e3.x + bb, e3.y + bb);
    }
}

// ---------------------------------------------------------------------------
// Launch
// ---------------------------------------------------------------------------
extern "C" void kernel_launch(void* const* d_in, const int* in_sizes, int n_in,
                              void* d_out, int out_size)
{
    (void)in_sizes; (void)n_in; (void)out_size;
    const float* x     = (const float*)d_in[0];
    const float* w_q   = (const float*)d_in[1];
    const float* w_k   = (const float*)d_in[2];
    const float* w_v   = (const float*)d_in[3];
    const float* w_o   = (const float*)d_in[4];
    const float* b_o   = (const float*)d_in[5];
    const float* rel_h = (const float*)d_in[6];
    const float* rel_w = (const float*)d_in[7];
    float* out = (float*)d_out;

    cudaFuncSetAttribute(flash_kernel,
                         cudaFuncAttributeMaxDynamicSharedMemorySize,
                         FL_SMEM_BYTES);

    transpose_w_kernel<<<dim3(16, 16, 4), 256>>>(w_q, w_k, w_v, w_o);
    qkv_kernel<<<dim3(8, 4, 48), 256>>>(x);
    transpose_v_kernel<<<dim3(16, 128), 256>>>();
    flash_kernel<<<dim3(16, 128), 256, FL_SMEM_BYTES>>>(rel_h, rel_w);
    out_proj_kernel<<<dim3(8, 4, 16), 256>>>(b_o, out);
}

// round 16
// speedup vs baseline: 1.5461x; 1.3933x over previous
#include <cuda_runtime.h>

// ---------------------------------------------------------------------------
// BottleNeck MHSA: B=16, C=512, H=W=32 (N=1024), NH=8, DK=64.
// Projections: fp32 FFMA2 (fma.rn.f32x2). Flash attention: tf32 tensor cores
// via mma.sync.m16n8k8 (S = Q.K^T and O = P.V), fragment-layout softmax.
// ---------------------------------------------------------------------------

#define Bsz 16
#define Cch 512
#define NPIX 1024
#define NHh 8
#define DKd 64
#define BH 128

typedef unsigned long long ull;

__device__ __forceinline__ ull dupf(float x) {
    ull d;
    asm("mov.b64 %0, {%1, %1};" : "=l"(d) : "r"(__float_as_uint(x)));
    return d;
}
__device__ __forceinline__ void ffma2(ull& d, ull a, ull b) {
    asm("fma.rn.f32x2 %0, %1, %2, %3;" : "=l"(d) : "l"(a), "l"(b), "l"(d));
}
__device__ __forceinline__ float2 unpk(ull v) {
    unsigned lo, hi;
    asm("mov.b64 {%0, %1}, %2;" : "=r"(lo), "=r"(hi) : "l"(v));
    return make_float2(__uint_as_float(lo), __uint_as_float(hi));
}
__device__ __forceinline__ unsigned f2tf(float x) {
    unsigned r;
    asm("cvt.rna.tf32.f32 %0, %1;" : "=r"(r) : "f"(x));
    return r;
}
__device__ __forceinline__ void mma_tf32(float* d, const unsigned* a,
                                         unsigned b0, unsigned b1) {
    asm volatile(
        "mma.sync.aligned.m16n8k8.row.col.f32.tf32.tf32.f32 "
        "{%0,%1,%2,%3}, {%4,%5,%6,%7}, {%8,%9}, {%0,%1,%2,%3};"
        : "+f"(d[0]), "+f"(d[1]), "+f"(d[2]), "+f"(d[3])
        : "r"(a[0]), "r"(a[1]), "r"(a[2]), "r"(a[3]), "r"(b0), "r"(b1));
}

__device__ float g_wt[4 * 512 * 512];        // transposed weights (c, o) x {q,k,v,o}
__device__ float g_q [BH * DKd * NPIX];      // (bh, dk, n)
__device__ float g_k [BH * DKd * NPIX];      // (bh, dk, n)
__device__ float g_vt[BH * DKd * NPIX];      // (bh, dk, n)  pre-transpose
__device__ float g_v [BH * NPIX * DKd];      // (bh, n, dk)
__device__ float g_o [Bsz * Cch * NPIX];     // (b, c=nh*64+d, n)

// ---------------------------------------------------------------------------
// Kernel 0: transpose the four 512x512 weight matrices into (c, o) layout.
// ---------------------------------------------------------------------------
__global__ __launch_bounds__(256) void transpose_w_kernel(
    const float* __restrict__ wq, const float* __restrict__ wk,
    const float* __restrict__ wv, const float* __restrict__ wo)
{
    __shared__ float t[32][33];
    const float* w = (blockIdx.z == 0) ? wq : (blockIdx.z == 1) ? wk
                   : (blockIdx.z == 2) ? wv : wo;
    float* wt = g_wt + (size_t)blockIdx.z * 512 * 512;
    const int c0 = blockIdx.x * 32, o0 = blockIdx.y * 32;
    const int tx = threadIdx.x & 31, ty = threadIdx.x >> 5;
#pragma unroll
    for (int i = 0; i < 4; i++)
        t[ty + i * 8][tx] = w[(o0 + ty + i * 8) * 512 + c0 + tx];
    __syncthreads();
#pragma unroll
    for (int i = 0; i < 4; i++)
        wt[(c0 + ty + i * 8) * 512 + o0 + tx] = t[tx][ty + i * 8];
}

// ---------------------------------------------------------------------------
// Kernel 1: QKV projection. 128x128 tile, K-tile 16, 8x8 micro via FFMA2.
// ---------------------------------------------------------------------------
__global__ __launch_bounds__(256, 2) void qkv_kernel(const float* __restrict__ x)
{
    const int nt = blockIdx.x, mt = blockIdx.y;
    const int z = blockIdx.z;
    const int b = z / 3, wsel = z - 3 * b;
    const int o0 = mt * 128, n0 = nt * 128;
    const float* wt = g_wt + (size_t)wsel * 512 * 512;
    const float* xb = x + (size_t)b * Cch * NPIX;

    __shared__ __align__(16) float As[2][16 * 128];
    __shared__ __align__(16) float Bs[2][16 * 128];

    const int tid = threadIdx.x;
    const int tx = tid & 15, ty = tid >> 4;

    ull acc2[8][4];
#pragma unroll
    for (int r = 0; r < 8; r++)
#pragma unroll
        for (int c = 0; c < 4; c++) acc2[r][c] = 0ull;

    const int lkk0 = (tid + 0 * 256) >> 5, lc40 = ((tid + 0 * 256) & 31) * 4;
    const int lkk1 = (tid + 1 * 256) >> 5, lc41 = ((tid + 1 * 256) & 31) * 4;

    float4 pa0, pa1, pb0, pb1;
    pa0 = *(const float4*)&wt[lkk0 * 512 + o0 + lc40];
    pa1 = *(const float4*)&wt[lkk1 * 512 + o0 + lc41];
    pb0 = *(const float4*)&xb[lkk0 * 1024 + n0 + lc40];
    pb1 = *(const float4*)&xb[lkk1 * 1024 + n0 + lc41];
    *(float4*)&As[0][lkk0 * 128 + lc40] = pa0;
    *(float4*)&As[0][lkk1 * 128 + lc41] = pa1;
    *(float4*)&Bs[0][lkk0 * 128 + lc40] = pb0;
    *(float4*)&Bs[0][lkk1 * 128 + lc41] = pb1;

#pragma unroll 1
    for (int kt = 0; kt < 32; kt++) {
        __syncthreads();
        const int cur = kt & 1;
        if (kt < 31) {
            const int c0 = (kt + 1) * 16;
            pa0 = *(const float4*)&wt[(c0 + lkk0) * 512 + o0 + lc40];
            pa1 = *(const float4*)&wt[(c0 + lkk1) * 512 + o0 + lc41];
            pb0 = *(const float4*)&xb[(c0 + lkk0) * 1024 + n0 + lc40];
            pb1 = *(const float4*)&xb[(c0 + lkk1) * 1024 + n0 + lc41];
        }
#pragma unroll 8
        for (int kk = 0; kk < 16; kk++) {
            float4 a0 = *(float4*)&As[cur][kk * 128 + ty * 4];
            float4 a1 = *(float4*)&As[cur][kk * 128 + 64 + ty * 4];
            ulonglong2 b0 = *(ulonglong2*)&Bs[cur][kk * 128 + tx * 4];
            ulonglong2 b1 = *(ulonglong2*)&Bs[cur][kk * 128 + 64 + tx * 4];
            ull bv[4] = {b0.x, b0.y, b1.x, b1.y};
            ull ad[8] = {dupf(a0.x), dupf(a0.y), dupf(a0.z), dupf(a0.w),
                         dupf(a1.x), dupf(a1.y), dupf(a1.z), dupf(a1.w)};
#pragma unroll
            for (int r = 0; r < 8; r++)
#pragma unroll
                for (int c = 0; c < 4; c++) ffma2(acc2[r][c], ad[r], bv[c]);
        }
        if (kt < 31) {
            const int nxt = cur ^ 1;
            *(float4*)&As[nxt][lkk0 * 128 + lc40] = pa0;
            *(float4*)&As[nxt][lkk1 * 128 + lc41] = pa1;
            *(float4*)&Bs[nxt][lkk0 * 128 + lc40] = pb0;
            *(float4*)&Bs[nxt][lkk1 * 128 + lc41] = pb1;
        }
    }

    float* dst = (wsel == 0) ? g_q : (wsel == 1) ? g_k : g_vt;
#pragma unroll
    for (int r = 0; r < 8; r++) {
        const int o = o0 + ((r < 4) ? (ty * 4 + r) : (64 + ty * 4 + r - 4));
        const int nh = o & 7, dk = o >> 3;
        const int bh = b * 8 + nh;
        float* p = dst + ((size_t)bh * 64 + dk) * 1024 + n0;
        float2 e0 = unpk(acc2[r][0]), e1 = unpk(acc2[r][1]);
        float2 e2 = unpk(acc2[r][2]), e3 = unpk(acc2[r][3]);
        *(float4*)&p[tx * 4]      = make_float4(e0.x, e0.y, e1.x, e1.y);
        *(float4*)&p[64 + tx * 4] = make_float4(e2.x, e2.y, e3.x, e3.y);
    }
}

// ---------------------------------------------------------------------------
// Kernel 2: transpose V (bh, dk, n) -> (bh, n, dk).
// ---------------------------------------------------------------------------
__global__ __launch_bounds__(256) void transpose_v_kernel()
{
    __shared__ float t[64][65];
    const int bh = blockIdx.y, n0 = blockIdx.x * 64;
    const float* src = g_vt + (size_t)bh * 64 * 1024;
    float* dst = g_v + (size_t)bh * 1024 * 64;
#pragma unroll
    for (int i = 0; i < 16; i++) {
        int id = threadIdx.x + i * 256;
        int d = id >> 6, n = id & 63;
        t[d][n] = src[d * 1024 + n0 + n];
    }
    __syncthreads();
#pragma unroll
    for (int i = 0; i < 16; i++) {
        int id = threadIdx.x + i * 256;
        int n = id >> 6, d = id & 63;
        dst[(size_t)(n0 + n) * 64 + d] = t[d][n];
    }
}

// ---------------------------------------------------------------------------
// Kernel 3: flash attention with tf32 mma.sync.m16n8k8.
// CTA = 128 threads (4 warps), q-tile 64 (16 q-rows per warp), key-tiles 64.
// ---------------------------------------------------------------------------
#define KSS 72   // K tile stride (pad: conflict-free B-frag loads)
#define VSS 72   // V tile stride
#define PSS 68   // P / Q / staging stride (conflict-free A-frag loads)
#define FL_KS  0
#define FL_VS  (FL_KS + 64 * KSS)
#define FL_PS  (FL_VS + 64 * VSS)
#define FL_RBH (FL_PS + 64 * PSS)
#define FL_RBW (FL_RBH + 64 * 33)
#define FL_TOT_FLOATS (FL_RBW + 64 * 36)
#define FL_SMEM_BYTES (FL_TOT_FLOATS * 4)

__global__ __launch_bounds__(128, 3) void flash_kernel(
    const float* __restrict__ rel_h, const float* __restrict__ rel_w)
{
    extern __shared__ __align__(16) float sm[];
    float*    Ks  = sm + FL_KS;  unsigned* Ksu = (unsigned*)Ks;
    float*    Vs  = sm + FL_VS;  unsigned* Vsu = (unsigned*)Vs;
    float*    Ps  = sm + FL_PS;  unsigned* Psu = (unsigned*)Ps;
    float*    Qs  = Ps;          // Qs consumed before Ps is first written
    float*    RBh = sm + FL_RBH;
    float*    RBw = sm + FL_RBW;

    const int qt = blockIdx.x;      // 0..15
    const int bh = blockIdx.y;      // 0..127
    const int b = bh >> 3, nh = bh & 7;
    const int q0 = qt * 64;
    const int tid = threadIdx.x;
    const int lane = tid & 31, warp = tid >> 5;
    const int gi = lane >> 2, gm = lane & 3;
    const int q0w = warp * 16;
    const int r0 = q0w + gi, r1 = r0 + 8;   // CTA-local q rows of this thread

    const float* qg = g_q + (size_t)bh * 64 * 1024;
    const float* kg = g_k + (size_t)bh * 64 * 1024;
    const float* vg = g_v + (size_t)bh * 1024 * 64;

    // ---- Q tile -> Qs[dk][PSS], scaled by 1/sqrt(DK)=0.125 ----
#pragma unroll
    for (int i = 0; i < 8; i++) {
        int id = tid + i * 128;
        int dk = id >> 4, c4 = (id & 15) * 4;
        float4 t = *(const float4*)&qg[dk * 1024 + q0 + c4];
        t.x *= 0.125f; t.y *= 0.125f; t.z *= 0.125f; t.w *= 0.125f;
        *(float4*)&Qs[dk * PSS + c4] = t;
    }
    __syncthreads();

    // ---- bias tables: RBh[p][i]=q_p.rel_h[i-xp+31], RBw[p][j]=q_p.rel_w[j-yp+31]
    {
        const int p = tid & 63;
        const int cbase = (tid >> 6) * 32;   // 0 or 32
        float myq[64];
#pragma unroll
        for (int dk = 0; dk < 64; dk++) myq[dk] = Qs[dk * PSS + p];
        const int xp = qt * 2 + (p >> 5);
        const int yp = p & 31;
#pragma unroll
        for (int j = 0; j < 32; j++) {
            const int c = cbase + j;
            const float* rr = (c < 32) ? (rel_h + (c - xp + 31) * 64)
                                       : (rel_w + ((c - 32) - yp + 31) * 64);
            float s = 0.f;
#pragma unroll
            for (int k4 = 0; k4 < 16; k4++) {
                float4 r4 = *(const float4*)&rr[k4 * 4];
                s += myq[k4 * 4 + 0] * r4.x + myq[k4 * 4 + 1] * r4.y
                   + myq[k4 * 4 + 2] * r4.z + myq[k4 * 4 + 3] * r4.w;
            }
            if (c < 32) RBh[p * 33 + c] = s;
            else        RBw[p * 36 + (c - 32)] = s;
        }
    }

    // ---- Q fragments (held in registers for the whole kernel) ----
    unsigned qa[8][4];
#pragma unroll
    for (int ks = 0; ks < 8; ks++) {
        qa[ks][0] = f2tf(Qs[(ks * 8 + gm) * PSS + q0w + gi]);
        qa[ks][1] = f2tf(Qs[(ks * 8 + gm) * PSS + q0w + gi + 8]);
        qa[ks][2] = f2tf(Qs[(ks * 8 + 4 + gm) * PSS + q0w + gi]);
        qa[ks][3] = f2tf(Qs[(ks * 8 + 4 + gm) * PSS + q0w + gi + 8]);
    }

    float m0 = -1e30f, m1 = -1e30f, l0 = 0.f, l1 = 0.f;
    float oacc[8][4];
#pragma unroll
    for (int n2 = 0; n2 < 8; n2++)
#pragma unroll
        for (int c = 0; c < 4; c++) oacc[n2][c] = 0.f;

#pragma unroll 1
    for (int kt = 0; kt < 16; kt++) {
        __syncthreads();   // also orders Qs-read (pre-loop) before Ps writes
        // K tile (dk-major) and V tile (key-major), tf32-converted
#pragma unroll
        for (int i = 0; i < 8; i++) {
            int id = tid + i * 128;
            int r_ = id >> 4, c4 = (id & 15) * 4;
            float4 t = *(const float4*)&kg[r_ * 1024 + kt * 64 + c4];
            uint4 u = make_uint4(f2tf(t.x), f2tf(t.y), f2tf(t.z), f2tf(t.w));
            *(uint4*)&Ksu[r_ * KSS + c4] = u;
            float4 v = *(const float4*)&vg[(size_t)(kt * 64 + r_) * 64 + c4];
            uint4 w = make_uint4(f2tf(v.x), f2tf(v.y), f2tf(v.z), f2tf(v.w));
            *(uint4*)&Vsu[r_ * VSS + c4] = w;
        }
        __syncthreads();

        // ---- S = Q.K^T : 64 mma per warp ----
        float sacc[8][4];
#pragma unroll
        for (int n = 0; n < 8; n++)
#pragma unroll
            for (int c = 0; c < 4; c++) sacc[n][c] = 0.f;
#pragma unroll
        for (int ks = 0; ks < 8; ks++) {
#pragma unroll
            for (int n = 0; n < 8; n++) {
                unsigned b0 = Ksu[(ks * 8 + gm) * KSS + n * 8 + gi];
                unsigned b1 = Ksu[(ks * 8 + 4 + gm) * KSS + n * 8 + gi];
                mma_tf32(sacc[n], qa[ks], b0, b1);
            }
        }

        // ---- bias add + row max (C layout: rows r0/r1, cols 2gm,2gm+1) ----
        float mx0 = -1e30f, mx1 = -1e30f;
#pragma unroll
        for (int n = 0; n < 8; n++) {
            const int ih = kt * 2 + (n >> 2);
            const int j = (n & 3) * 8 + gm * 2;
            float hA = RBh[r0 * 33 + ih], hB = RBh[r1 * 33 + ih];
            float2 w0 = *(float2*)&RBw[r0 * 36 + j];
            float2 w1 = *(float2*)&RBw[r1 * 36 + j];
            sacc[n][0] += hA + w0.x; sacc[n][1] += hA + w0.y;
            sacc[n][2] += hB + w1.x; sacc[n][3] += hB + w1.y;
            mx0 = fmaxf(mx0, fmaxf(sacc[n][0], sacc[n][1]));
            mx1 = fmaxf(mx1, fmaxf(sacc[n][2], sacc[n][3]));
        }
        mx0 = fmaxf(mx0, __shfl_xor_sync(0xffffffffu, mx0, 1));
        mx0 = fmaxf(mx0, __shfl_xor_sync(0xffffffffu, mx0, 2));
        mx1 = fmaxf(mx1, __shfl_xor_sync(0xffffffffu, mx1, 1));
        mx1 = fmaxf(mx1, __shfl_xor_sync(0xffffffffu, mx1, 2));

        float nm0 = fmaxf(m0, mx0), nm1 = fmaxf(m1, mx1);
        float f0 = __expf(m0 - nm0), f1 = __expf(m1 - nm1);
        m0 = nm0; m1 = nm1;

        float rs0 = 0.f, rs1 = 0.f;
#pragma unroll
        for (int n = 0; n < 8; n++) {
            float e0 = __expf(sacc[n][0] - m0), e1 = __expf(sacc[n][1] - m0);
            float e2 = __expf(sacc[n][2] - m1), e3 = __expf(sacc[n][3] - m1);
            rs0 += e0 + e1; rs1 += e2 + e3;
            *(uint2*)&Psu[r0 * PSS + n * 8 + gm * 2] = make_uint2(f2tf(e0), f2tf(e1));
            *(uint2*)&Psu[r1 * PSS + n * 8 + gm * 2] = make_uint2(f2tf(e2), f2tf(e3));
        }
        rs0 += __shfl_xor_sync(0xffffffffu, rs0, 1);
        rs0 += __shfl_xor_sync(0xffffffffu, rs0, 2);
        rs1 += __shfl_xor_sync(0xffffffffu, rs1, 1);
        rs1 += __shfl_xor_sync(0xffffffffu, rs1, 2);
        l0 = l0 * f0 + rs0;
        l1 = l1 * f1 + rs1;
#pragma unroll
        for (int n2 = 0; n2 < 8; n2++) {
            oacc[n2][0] *= f0; oacc[n2][1] *= f0;
            oacc[n2][2] *= f1; oacc[n2][3] *= f1;
        }
        __syncwarp();   // Ps rows are warp-private; order stores before loads

        // ---- O += P.V : 64 mma per warp ----
#pragma unroll
        for (int ks = 0; ks < 8; ks++) {
            unsigned pa[4];
            pa[0] = Psu[r0 * PSS + ks * 8 + gm];
            pa[1] = Psu[r1 * PSS + ks * 8 + gm];
            pa[2] = Psu[r0 * PSS + ks * 8 + 4 + gm];
            pa[3] = Psu[r1 * PSS + ks * 8 + 4 + gm];
#pragma unroll
            for (int n2 = 0; n2 < 8; n2++) {
                unsigned b0 = Vsu[(ks * 8 + gm) * VSS + n2 * 8 + gi];
                unsigned b1 = Vsu[(ks * 8 + 4 + gm) * VSS + n2 * 8 + gi];
                mma_tf32(oacc[n2], pa, b0, b1);
            }
        }
    }

    // ---- epilogue: normalize, stage fp32 in Ps, coalesced write ----
    float inv0 = 1.f / l0, inv1 = 1.f / l1;
#pragma unroll
    for (int n2 = 0; n2 < 8; n2++) {
        *(float2*)&Ps[r0 * PSS + n2 * 8 + gm * 2] =
            make_float2(oacc[n2][0] * inv0, oacc[n2][1] * inv0);
        *(float2*)&Ps[r1 * PSS + n2 * 8 + gm * 2] =
            make_float2(oacc[n2][2] * inv1, oacc[n2][3] * inv1);
    }
    __syncthreads();
    float* og = g_o + ((size_t)b * 512 + nh * 64) * 1024 + q0;
#pragma unroll
    for (int i = 0; i < 32; i++) {
        int id = tid + i * 128;
        int q = id & 63, d = id >> 6;
        og[d * 1024 + q] = Ps[q * PSS + d];
    }
}

// ---------------------------------------------------------------------------
// Kernel 4: output projection + bias (FFMA2).
// ---------------------------------------------------------------------------
__global__ __launch_bounds__(256, 2) void out_proj_kernel(
    const float* __restrict__ bo, float* __restrict__ out)
{
    const int nt = blockIdx.x, mt = blockIdx.y, b = blockIdx.z;
    const int o0 = mt * 128, n0 = nt * 128;
    const float* wt = g_wt + (size_t)3 * 512 * 512;
    const float* xb = g_o + (size_t)b * Cch * NPIX;

    __shared__ __align__(16) float As[2][16 * 128];
    __shared__ __align__(16) float Bs[2][16 * 128];

    const int tid = threadIdx.x;
    const int tx = tid & 15, ty = tid >> 4;

    ull acc2[8][4];
#pragma unroll
    for (int r = 0; r < 8; r++)
#pragma unroll
        for (int c = 0; c < 4; c++) acc2[r][c] = 0ull;

    const int lkk0 = (tid + 0 * 256) >> 5, lc40 = ((tid + 0 * 256) & 31) * 4;
    const int lkk1 = (tid + 1 * 256) >> 5, lc41 = ((tid + 1 * 256) & 31) * 4;

    float4 pa0, pa1, pb0, pb1;
    pa0 = *(const float4*)&wt[lkk0 * 512 + o0 + lc40];
    pa1 = *(const float4*)&wt[lkk1 * 512 + o0 + lc41];
    pb0 = *(const float4*)&xb[lkk0 * 1024 + n0 + lc40];
    pb1 = *(const float4*)&xb[lkk1 * 1024 + n0 + lc41];
    *(float4*)&As[0][lkk0 * 128 + lc40] = pa0;
    *(float4*)&As[0][lkk1 * 128 + lc41] = pa1;
    *(float4*)&Bs[0][lkk0 * 128 + lc40] = pb0;
    *(float4*)&Bs[0][lkk1 * 128 + lc41] = pb1;

#pragma unroll 1
    for (int kt = 0; kt < 32; kt++) {
        __syncthreads();
        const int cur = kt & 1;
        if (kt < 31) {
            const int c0 = (kt + 1) * 16;
            pa0 = *(const float4*)&wt[(c0 + lkk0) * 512 + o0 + lc40];
            pa1 = *(const float4*)&wt[(c0 + lkk1) * 512 + o0 + lc41];
            pb0 = *(const float4*)&xb[(c0 + lkk0) * 1024 + n0 + lc40];
            pb1 = *(const float4*)&xb[(c0 + lkk1) * 1024 + n0 + lc41];
        }
#pragma unroll 8
        for (int kk = 0; kk < 16; kk++) {
            float4 a0 = *(float4*)&As[cur][kk * 128 + ty * 4];
            float4 a1 = *(float4*)&As[cur][kk * 128 + 64 + ty * 4];
            ulonglong2 b0 = *(ulonglong2*)&Bs[cur][kk * 128 + tx * 4];
            ulonglong2 b1 = *(ulonglong2*)&Bs[cur][kk * 128 + 64 + tx * 4];
            ull bv[4] = {b0.x, b0.y, b1.x, b1.y};
            ull ad[8] = {dupf(a0.x), dupf(a0.y), dupf(a0.z), dupf(a0.w),
                         dupf(a1.x), dupf(a1.y), dupf(a1.z), dupf(a1.w)};
#pragma unroll
            for (int r = 0; r < 8; r++)
#pragma unroll
                for (int c = 0; c < 4; c++) ffma2(acc2[r][c], ad[r], bv[c]);
        }
        if (kt < 31) {
            const int nxt = cur ^ 1;
            *(float4*)&As[nxt][lkk0 * 128 + lc40] = pa0;
            *(float4*)&As[nxt][lkk1 * 128 + lc41] = pa1;
            *(float4*)&Bs[nxt][lkk0 * 128 + lc40] = pb0;
            *(float4*)&Bs[nxt][lkk1 * 128 + lc41] = pb1;
        }
    }

#pragma unroll
    for (int r = 0; r < 8; r++) {
        const int o = o0 + ((r < 4) ? (ty * 4 + r) : (64 + ty * 4 + r - 4));
        const float bb = bo[o];
        float* p = out + ((size_t)b * 512 + o) * 1024 + n0;
        float2 e0 = unpk(acc2[r][0]), e1 = unpk(acc2[r][1]);
        float2 e2 = unpk(acc2[r][2]), e3 = unpk(acc2[r][3]);
        *(float4*)&p[tx * 4] = make_float4(e0.x + bb, e0.y + bb, e1.x + bb, e1.y + bb);
        *(float4*)&p[64 + tx * 4] = make_float4(e2.x + bb, e2.y + bb, e3.x + bb, e3.y + bb);
    }
}

// ---------------------------------------------------------------------------
// Launch
// ---------------------------------------------------------------------------
extern "C" void kernel_launch(void* const* d_in, const int* in_sizes, int n_in,
                              void* d_out, int out_size)
{
    (void)in_sizes; (void)n_in; (void)out_size;
    const float* x     = (const float*)d_in[0];
    const float* w_q   = (const float*)d_in[1];
    const float* w_k   = (const float*)d_in[2];
    const float* w_v   = (const float*)d_in[3];
    const float* w_o   = (const float*)d_in[4];
    const float* b_o   = (const float*)d_in[5];
    const float* rel_h = (const float*)d_in[6];
    const float* rel_w = (const float*)d_in[7];
    float* out = (float*)d_out;

    cudaFuncSetAttribute(flash_kernel,
                         cudaFuncAttributeMaxDynamicSharedMemorySize,
                         FL_SMEM_BYTES);

    transpose_w_kernel<<<dim3(16, 16, 4), 256>>>(w_q, w_k, w_v, w_o);
    qkv_kernel<<<dim3(8, 4, 48), 256>>>(x);
    transpose_v_kernel<<<dim3(16, 128), 256>>>();
    flash_kernel<<<dim3(16, 128), 128, FL_SMEM_BYTES>>>(rel_h, rel_w);
    out_proj_kernel<<<dim3(8, 4, 16), 256>>>(b_o, out);
}

// round 17
// speedup vs baseline: 1.5660x; 1.0129x over previous
#include <cuda_runtime.h>

// ---------------------------------------------------------------------------
// BottleNeck MHSA: B=16, C=512, H=W=32 (N=1024), NH=8, DK=64.
// Projections: fp32 FFMA2. Flash attention: tf32 mma.sync.m16n8k8,
// 4 CTAs/SM (shared K/V smem buffer), cp.async tile loads (K/V pre-rounded
// to tf32 by producers), exp2-domain softmax.
// ---------------------------------------------------------------------------

#define Bsz 16
#define Cch 512
#define NPIX 1024
#define NHh 8
#define DKd 64
#define BH 128

typedef unsigned long long ull;

__device__ __forceinline__ ull dupf(float x) {
    ull d;
    asm("mov.b64 %0, {%1, %1};" : "=l"(d) : "r"(__float_as_uint(x)));
    return d;
}
__device__ __forceinline__ void ffma2(ull& d, ull a, ull b) {
    asm("fma.rn.f32x2 %0, %1, %2, %3;" : "=l"(d) : "l"(a), "l"(b), "l"(d));
}
__device__ __forceinline__ float2 unpk(ull v) {
    unsigned lo, hi;
    asm("mov.b64 {%0, %1}, %2;" : "=r"(lo), "=r"(hi) : "l"(v));
    return make_float2(__uint_as_float(lo), __uint_as_float(hi));
}
__device__ __forceinline__ unsigned f2tf(float x) {
    unsigned r;
    asm("cvt.rna.tf32.f32 %0, %1;" : "=r"(r) : "f"(x));
    return r;
}
__device__ __forceinline__ float tf32r(float x) {
    return __uint_as_float(f2tf(x));
}
__device__ __forceinline__ float ex2f(float x) {
    float y;
    asm("ex2.approx.f32 %0, %1;" : "=f"(y) : "f"(x));
    return y;
}
__device__ __forceinline__ void mma_tf32(float* d, const unsigned* a,
                                         unsigned b0, unsigned b1) {
    asm volatile(
        "mma.sync.aligned.m16n8k8.row.col.f32.tf32.tf32.f32 "
        "{%0,%1,%2,%3}, {%4,%5,%6,%7}, {%8,%9}, {%0,%1,%2,%3};"
        : "+f"(d[0]), "+f"(d[1]), "+f"(d[2]), "+f"(d[3])
        : "r"(a[0]), "r"(a[1]), "r"(a[2]), "r"(a[3]), "r"(b0), "r"(b1));
}
#define CP_ASYNC16(dst_u32, src_ptr) \
    asm volatile("cp.async.ca.shared.global [%0], [%1], 16;" \
                 :: "r"(dst_u32), "l"(src_ptr))
#define CP_COMMIT()  asm volatile("cp.async.commit_group;")
#define CP_WAIT0()   asm volatile("cp.async.wait_group 0;")

// 0.125 * log2(e): folds the 1/sqrt(DK) scale AND the exp->exp2 base change
#define QSC 0.1803368801111204f

__device__ float g_wt[4 * 512 * 512];        // transposed weights (c, o) x {q,k,v,o}
__device__ float g_q [BH * DKd * NPIX];      // (bh, dk, n)
__device__ float g_k [BH * DKd * NPIX];      // (bh, dk, n)  tf32-rounded
__device__ float g_vt[BH * DKd * NPIX];      // (bh, dk, n)  pre-transpose
__device__ float g_v [BH * NPIX * DKd];      // (bh, n, dk)  tf32-rounded
__device__ float g_o [Bsz * Cch * NPIX];     // (b, c=nh*64+d, n)

// ---------------------------------------------------------------------------
// Kernel 0: transpose the four 512x512 weight matrices into (c, o) layout.
// ---------------------------------------------------------------------------
__global__ __launch_bounds__(256) void transpose_w_kernel(
    const float* __restrict__ wq, const float* __restrict__ wk,
    const float* __restrict__ wv, const float* __restrict__ wo)
{
    __shared__ float t[32][33];
    const float* w = (blockIdx.z == 0) ? wq : (blockIdx.z == 1) ? wk
                   : (blockIdx.z == 2) ? wv : wo;
    float* wt = g_wt + (size_t)blockIdx.z * 512 * 512;
    const int c0 = blockIdx.x * 32, o0 = blockIdx.y * 32;
    const int tx = threadIdx.x & 31, ty = threadIdx.x >> 5;
#pragma unroll
    for (int i = 0; i < 4; i++)
        t[ty + i * 8][tx] = w[(o0 + ty + i * 8) * 512 + c0 + tx];
    __syncthreads();
#pragma unroll
    for (int i = 0; i < 4; i++)
        wt[(c0 + ty + i * 8) * 512 + o0 + tx] = t[tx][ty + i * 8];
}

// ---------------------------------------------------------------------------
// Kernel 1: QKV projection. 128x128 tile, K-tile 16, 8x8 micro via FFMA2.
// K output (wsel==1) is tf32-rounded for the flash tensor-core path.
// ---------------------------------------------------------------------------
__global__ __launch_bounds__(256, 2) void qkv_kernel(const float* __restrict__ x)
{
    const int nt = blockIdx.x, mt = blockIdx.y;
    const int z = blockIdx.z;
    const int b = z / 3, wsel = z - 3 * b;
    const int o0 = mt * 128, n0 = nt * 128;
    const float* wt = g_wt + (size_t)wsel * 512 * 512;
    const float* xb = x + (size_t)b * Cch * NPIX;

    __shared__ __align__(16) float As[2][16 * 128];
    __shared__ __align__(16) float Bs[2][16 * 128];

    const int tid = threadIdx.x;
    const int tx = tid & 15, ty = tid >> 4;

    ull acc2[8][4];
#pragma unroll
    for (int r = 0; r < 8; r++)
#pragma unroll
        for (int c = 0; c < 4; c++) acc2[r][c] = 0ull;

    const int lkk0 = (tid + 0 * 256) >> 5, lc40 = ((tid + 0 * 256) & 31) * 4;
    const int lkk1 = (tid + 1 * 256) >> 5, lc41 = ((tid + 1 * 256) & 31) * 4;

    float4 pa0, pa1, pb0, pb1;
    pa0 = *(const float4*)&wt[lkk0 * 512 + o0 + lc40];
    pa1 = *(const float4*)&wt[lkk1 * 512 + o0 + lc41];
    pb0 = *(const float4*)&xb[lkk0 * 1024 + n0 + lc40];
    pb1 = *(const float4*)&xb[lkk1 * 1024 + n0 + lc41];
    *(float4*)&As[0][lkk0 * 128 + lc40] = pa0;
    *(float4*)&As[0][lkk1 * 128 + lc41] = pa1;
    *(float4*)&Bs[0][lkk0 * 128 + lc40] = pb0;
    *(float4*)&Bs[0][lkk1 * 128 + lc41] = pb1;

#pragma unroll 1
    for (int kt = 0; kt < 32; kt++) {
        __syncthreads();
        const int cur = kt & 1;
        if (kt < 31) {
            const int c0 = (kt + 1) * 16;
            pa0 = *(const float4*)&wt[(c0 + lkk0) * 512 + o0 + lc40];
            pa1 = *(const float4*)&wt[(c0 + lkk1) * 512 + o0 + lc41];
            pb0 = *(const float4*)&xb[(c0 + lkk0) * 1024 + n0 + lc40];
            pb1 = *(const float4*)&xb[(c0 + lkk1) * 1024 + n0 + lc41];
        }
#pragma unroll 8
        for (int kk = 0; kk < 16; kk++) {
            float4 a0 = *(float4*)&As[cur][kk * 128 + ty * 4];
            float4 a1 = *(float4*)&As[cur][kk * 128 + 64 + ty * 4];
            ulonglong2 b0 = *(ulonglong2*)&Bs[cur][kk * 128 + tx * 4];
            ulonglong2 b1 = *(ulonglong2*)&Bs[cur][kk * 128 + 64 + tx * 4];
            ull bv[4] = {b0.x, b0.y, b1.x, b1.y};
            ull ad[8] = {dupf(a0.x), dupf(a0.y), dupf(a0.z), dupf(a0.w),
                         dupf(a1.x), dupf(a1.y), dupf(a1.z), dupf(a1.w)};
#pragma unroll
            for (int r = 0; r < 8; r++)
#pragma unroll
                for (int c = 0; c < 4; c++) ffma2(acc2[r][c], ad[r], bv[c]);
        }
        if (kt < 31) {
            const int nxt = cur ^ 1;
            *(float4*)&As[nxt][lkk0 * 128 + lc40] = pa0;
            *(float4*)&As[nxt][lkk1 * 128 + lc41] = pa1;
            *(float4*)&Bs[nxt][lkk0 * 128 + lc40] = pb0;
            *(float4*)&Bs[nxt][lkk1 * 128 + lc41] = pb1;
        }
    }

    float* dst = (wsel == 0) ? g_q : (wsel == 1) ? g_k : g_vt;
    const bool rnd = (wsel == 1);
#pragma unroll
    for (int r = 0; r < 8; r++) {
        const int o = o0 + ((r < 4) ? (ty * 4 + r) : (64 + ty * 4 + r - 4));
        const int nh = o & 7, dk = o >> 3;
        const int bh = b * 8 + nh;
        float* p = dst + ((size_t)bh * 64 + dk) * 1024 + n0;
        float2 e0 = unpk(acc2[r][0]), e1 = unpk(acc2[r][1]);
        float2 e2 = unpk(acc2[r][2]), e3 = unpk(acc2[r][3]);
        float4 v0 = make_float4(e0.x, e0.y, e1.x, e1.y);
        float4 v1 = make_float4(e2.x, e2.y, e3.x, e3.y);
        if (rnd) {
            v0 = make_float4(tf32r(v0.x), tf32r(v0.y), tf32r(v0.z), tf32r(v0.w));
            v1 = make_float4(tf32r(v1.x), tf32r(v1.y), tf32r(v1.z), tf32r(v1.w));
        }
        *(float4*)&p[tx * 4]      = v0;
        *(float4*)&p[64 + tx * 4] = v1;
    }
}

// ---------------------------------------------------------------------------
// Kernel 2: transpose V (bh, dk, n) -> (bh, n, dk), tf32-rounding on store.
// ---------------------------------------------------------------------------
__global__ __launch_bounds__(256) void transpose_v_kernel()
{
    __shared__ float t[64][65];
    const int bh = blockIdx.y, n0 = blockIdx.x * 64;
    const float* src = g_vt + (size_t)bh * 64 * 1024;
    float* dst = g_v + (size_t)bh * 1024 * 64;
#pragma unroll
    for (int i = 0; i < 16; i++) {
        int id = threadIdx.x + i * 256;
        int d = id >> 6, n = id & 63;
        t[d][n] = src[d * 1024 + n0 + n];
    }
    __syncthreads();
#pragma unroll
    for (int i = 0; i < 16; i++) {
        int id = threadIdx.x + i * 256;
        int n = id >> 6, d = id & 63;
        dst[(size_t)(n0 + n) * 64 + d] = tf32r(t[d][n]);
    }
}

// ---------------------------------------------------------------------------
// Kernel 3: flash attention, tf32 mma.sync.m16n8k8. 128 thr, 4 CTAs/SM.
// Shared K/V buffer (V overwrites K mid-iteration); cp.async tile loads;
// exp2-domain softmax (scale folded into Q).
// ---------------------------------------------------------------------------
#define KVS 72   // K/V tile stride (pad: conflict-free B-frag loads)
#define PSS 68   // P / Q / staging stride (conflict-free A-frag loads)
#define FL_KV  0
#define FL_PS  (FL_KV + 64 * KVS)
#define FL_RBH (FL_PS + 64 * PSS)
#define FL_RBW (FL_RBH + 64 * 33)
#define FL_TOT_FLOATS (FL_RBW + 64 * 36)
#define FL_SMEM_BYTES (FL_TOT_FLOATS * 4)

__global__ __launch_bounds__(128, 4) void flash_kernel(
    const float* __restrict__ rel_h, const float* __restrict__ rel_w)
{
    extern __shared__ __align__(16) float sm[];
    float*    KV  = sm + FL_KV;  unsigned* KVu = (unsigned*)KV;
    float*    Ps  = sm + FL_PS;  unsigned* Psu = (unsigned*)Ps;
    float*    Qs  = Ps;          // Qs consumed before Ps is first written
    float*    RBh = sm + FL_RBH;
    float*    RBw = sm + FL_RBW;

    const int qt = blockIdx.x;      // 0..15
    const int bh = blockIdx.y;      // 0..127
    const int b = bh >> 3, nh = bh & 7;
    const int q0 = qt * 64;
    const int tid = threadIdx.x;
    const int lane = tid & 31, warp = tid >> 5;
    const int gi = lane >> 2, gm = lane & 3;
    const int q0w = warp * 16;
    const int r0 = q0w + gi, r1 = r0 + 8;

    const float* qg = g_q + (size_t)bh * 64 * 1024;
    const float* kg = g_k + (size_t)bh * 64 * 1024;
    const float* vg = g_v + (size_t)bh * 1024 * 64;

    const unsigned kv_u32 =
        (unsigned)__cvta_generic_to_shared((const void*)KV);
    const int ldr = tid >> 4, ldc4 = (tid & 15) * 4;   // tile-copy coords

    // ---- Q tile -> Qs[dk][PSS], scaled by 0.125*log2e ----
#pragma unroll
    for (int i = 0; i < 8; i++) {
        int id = tid + i * 128;
        int dk = id >> 4, c4 = (id & 15) * 4;
        float4 t = *(const float4*)&qg[dk * 1024 + q0 + c4];
        t.x *= QSC; t.y *= QSC; t.z *= QSC; t.w *= QSC;
        *(float4*)&Qs[dk * PSS + c4] = t;
    }
    __syncthreads();

    // ---- bias tables (in exp2 domain automatically: built from scaled Q)
    {
        const int p = tid & 63;
        const int cbase = (tid >> 6) * 32;   // 0 or 32
        float myq[64];
#pragma unroll
        for (int dk = 0; dk < 64; dk++) myq[dk] = Qs[dk * PSS + p];
        const int xp = qt * 2 + (p >> 5);
        const int yp = p & 31;
#pragma unroll
        for (int j = 0; j < 32; j++) {
            const int c = cbase + j;
            const float* rr = (c < 32) ? (rel_h + (c - xp + 31) * 64)
                                       : (rel_w + ((c - 32) - yp + 31) * 64);
            float s = 0.f;
#pragma unroll
            for (int k4 = 0; k4 < 16; k4++) {
                float4 r4 = *(const float4*)&rr[k4 * 4];
                s += myq[k4 * 4 + 0] * r4.x + myq[k4 * 4 + 1] * r4.y
                   + myq[k4 * 4 + 2] * r4.z + myq[k4 * 4 + 3] * r4.w;
            }
            if (c < 32) RBh[p * 33 + c] = s;
            else        RBw[p * 36 + (c - 32)] = s;
        }
    }

    // ---- Q fragments (registers, whole kernel) ----
    unsigned qa[8][4];
#pragma unroll
    for (int ks = 0; ks < 8; ks++) {
        qa[ks][0] = f2tf(Qs[(ks * 8 + gm) * PSS + q0w + gi]);
        qa[ks][1] = f2tf(Qs[(ks * 8 + gm) * PSS + q0w + gi + 8]);
        qa[ks][2] = f2tf(Qs[(ks * 8 + 4 + gm) * PSS + q0w + gi]);
        qa[ks][3] = f2tf(Qs[(ks * 8 + 4 + gm) * PSS + q0w + gi + 8]);
    }

    float m0 = -1e30f, m1 = -1e30f, l0 = 0.f, l1 = 0.f;
    float oacc[8][4];
#pragma unroll
    for (int n2 = 0; n2 < 8; n2++)
#pragma unroll
        for (int c = 0; c < 4; c++) oacc[n2][c] = 0.f;

#pragma unroll 1
    for (int kt = 0; kt < 16; kt++) {
        __syncthreads();   // prev PV done (KV free); Qs-read done (kt=0)
        // ---- K tile (dk-major, pre-tf32) via cp.async ----
#pragma unroll
        for (int i = 0; i < 8; i++) {
            int id = tid + i * 128;
            int r_ = id >> 4, c4 = (id & 15) * 4;
            CP_ASYNC16(kv_u32 + (r_ * KVS + c4) * 4,
                       &kg[r_ * 1024 + kt * 64 + c4]);
        }
        CP_COMMIT();
        CP_WAIT0();
        __syncthreads();

        // ---- S = Q.K^T : 64 mma per warp ----
        float sacc[8][4];
#pragma unroll
        for (int n = 0; n < 8; n++)
#pragma unroll
            for (int c = 0; c < 4; c++) sacc[n][c] = 0.f;
#pragma unroll
        for (int ks = 0; ks < 8; ks++) {
#pragma unroll
            for (int n = 0; n < 8; n++) {
                unsigned b0 = KVu[(ks * 8 + gm) * KVS + n * 8 + gi];
                unsigned b1 = KVu[(ks * 8 + 4 + gm) * KVS + n * 8 + gi];
                mma_tf32(sacc[n], qa[ks], b0, b1);
            }
        }

        // ---- bias add + row max ----
        float mx0 = -1e30f, mx1 = -1e30f;
#pragma unroll
        for (int n = 0; n < 8; n++) {
            const int ih = kt * 2 + (n >> 2);
            const int j = (n & 3) * 8 + gm * 2;
            float hA = RBh[r0 * 33 + ih], hB = RBh[r1 * 33 + ih];
            float2 w0 = *(float2*)&RBw[r0 * 36 + j];
            float2 w1 = *(float2*)&RBw[r1 * 36 + j];
            sacc[n][0] += hA + w0.x; sacc[n][1] += hA + w0.y;
            sacc[n][2] += hB + w1.x; sacc[n][3] += hB + w1.y;
            mx0 = fmaxf(mx0, fmaxf(sacc[n][0], sacc[n][1]));
            mx1 = fmaxf(mx1, fmaxf(sacc[n][2], sacc[n][3]));
        }
        mx0 = fmaxf(mx0, __shfl_xor_sync(0xffffffffu, mx0, 1));
        mx0 = fmaxf(mx0, __shfl_xor_sync(0xffffffffu, mx0, 2));
        mx1 = fmaxf(mx1, __shfl_xor_sync(0xffffffffu, mx1, 1));
        mx1 = fmaxf(mx1, __shfl_xor_sync(0xffffffffu, mx1, 2));

        float nm0 = fmaxf(m0, mx0), nm1 = fmaxf(m1, mx1);
        float f0 = ex2f(m0 - nm0), f1 = ex2f(m1 - nm1);
        m0 = nm0; m1 = nm1;

        float rs0 = 0.f, rs1 = 0.f;
#pragma unroll
        for (int n = 0; n < 8; n++) {
            float e0 = ex2f(sacc[n][0] - m0), e1 = ex2f(sacc[n][1] - m0);
            float e2 = ex2f(sacc[n][2] - m1), e3 = ex2f(sacc[n][3] - m1);
            rs0 += e0 + e1; rs1 += e2 + e3;
            *(uint2*)&Psu[r0 * PSS + n * 8 + gm * 2] = make_uint2(f2tf(e0), f2tf(e1));
            *(uint2*)&Psu[r1 * PSS + n * 8 + gm * 2] = make_uint2(f2tf(e2), f2tf(e3));
        }
        rs0 += __shfl_xor_sync(0xffffffffu, rs0, 1);
        rs0 += __shfl_xor_sync(0xffffffffu, rs0, 2);
        rs1 += __shfl_xor_sync(0xffffffffu, rs1, 1);
        rs1 += __shfl_xor_sync(0xffffffffu, rs1, 2);
        l0 = l0 * f0 + rs0;
        l1 = l1 * f1 + rs1;
#pragma unroll
        for (int n2 = 0; n2 < 8; n2++) {
            oacc[n2][0] *= f0; oacc[n2][1] *= f0;
            oacc[n2][2] *= f1; oacc[n2][3] *= f1;
        }
        __syncthreads();   // all warps done reading K -> safe to overwrite

        // ---- V tile (key-major, pre-tf32) via cp.async into same buffer ----
#pragma unroll
        for (int i = 0; i < 8; i++) {
            int id = tid + i * 128;
            int r_ = id >> 4, c4 = (id & 15) * 4;
            CP_ASYNC16(kv_u32 + (r_ * KVS + c4) * 4,
                       &vg[(size_t)(kt * 64 + r_) * 64 + c4]);
        }
        CP_COMMIT();
        CP_WAIT0();
        __syncthreads();

        // ---- O += P.V : 64 mma per warp ----
#pragma unroll
        for (int ks = 0; ks < 8; ks++) {
            unsigned pa[4];
            pa[0] = Psu[r0 * PSS + ks * 8 + gm];
            pa[1] = Psu[r1 * PSS + ks * 8 + gm];
            pa[2] = Psu[r0 * PSS + ks * 8 + 4 + gm];
            pa[3] = Psu[r1 * PSS + ks * 8 + 4 + gm];
#pragma unroll
            for (int n2 = 0; n2 < 8; n2++) {
                unsigned b0 = KVu[(ks * 8 + gm) * KVS + n2 * 8 + gi];
                unsigned b1 = KVu[(ks * 8 + 4 + gm) * KVS + n2 * 8 + gi];
                mma_tf32(oacc[n2], pa, b0, b1);
            }
        }
    }

    // ---- epilogue: normalize, stage fp32 in Ps, coalesced write ----
    __syncthreads();   // all PV reads of Ps complete before overwrite
    float inv0 = 1.f / l0, inv1 = 1.f / l1;
#pragma unroll
    for (int n2 = 0; n2 < 8; n2++) {
        *(float2*)&Ps[r0 * PSS + n2 * 8 + gm * 2] =
            make_float2(oacc[n2][0] * inv0, oacc[n2][1] * inv0);
        *(float2*)&Ps[r1 * PSS + n2 * 8 + gm * 2] =
            make_float2(oacc[n2][2] * inv1, oacc[n2][3] * inv1);
    }
    __syncthreads();
    float* og = g_o + ((size_t)b * 512 + nh * 64) * 1024 + q0;
#pragma unroll
    for (int i = 0; i < 32; i++) {
        int id = tid + i * 128;
        int q = id & 63, d = id >> 6;
        og[d * 1024 + q] = Ps[q * PSS + d];
    }
}

// ---------------------------------------------------------------------------
// Kernel 4: output projection + bias (FFMA2).
// ---------------------------------------------------------------------------
__global__ __launch_bounds__(256, 2) void out_proj_kernel(
    const float* __restrict__ bo, float* __restrict__ out)
{
    const int nt = blockIdx.x, mt = blockIdx.y, b = blockIdx.z;
    const int o0 = mt * 128, n0 = nt * 128;
    const float* wt = g_wt + (size_t)3 * 512 * 512;
    const float* xb = g_o + (size_t)b * Cch * NPIX;

    __shared__ __align__(16) float As[2][16 * 128];
    __shared__ __align__(16) float Bs[2][16 * 128];

    const int tid = threadIdx.x;
    const int tx = tid & 15, ty = tid >> 4;

    ull acc2[8][4];
#pragma unroll
    for (int r = 0; r < 8; r++)
#pragma unroll
        for (int c = 0; c < 4; c++) acc2[r][c] = 0ull;

    const int lkk0 = (tid + 0 * 256) >> 5, lc40 = ((tid + 0 * 256) & 31) * 4;
    const int lkk1 = (tid + 1 * 256) >> 5, lc41 = ((tid + 1 * 256) & 31) * 4;

    float4 pa0, pa1, pb0, pb1;
    pa0 = *(const float4*)&wt[lkk0 * 512 + o0 + lc40];
    pa1 = *(const float4*)&wt[lkk1 * 512 + o0 + lc41];
    pb0 = *(const float4*)&xb[lkk0 * 1024 + n0 + lc40];
    pb1 = *(const float4*)&xb[lkk1 * 1024 + n0 + lc41];
    *(float4*)&As[0][lkk0 * 128 + lc40] = pa0;
    *(float4*)&As[0][lkk1 * 128 + lc41] = pa1;
    *(float4*)&Bs[0][lkk0 * 128 + lc40] = pb0;
    *(float4*)&Bs[0][lkk1 * 128 + lc41] = pb1;

#pragma unroll 1
    for (int kt = 0; kt < 32; kt++) {
        __syncthreads();
        const int cur = kt & 1;
        if (kt < 31) {
            const int c0 = (kt + 1) * 16;
            pa0 = *(const float4*)&wt[(c0 + lkk0) * 512 + o0 + lc40];
            pa1 = *(const float4*)&wt[(c0 + lkk1) * 512 + o0 + lc41];
            pb0 = *(const float4*)&xb[(c0 + lkk0) * 1024 + n0 + lc40];
            pb1 = *(const float4*)&xb[(c0 + lkk1) * 1024 + n0 + lc41];
        }
#pragma unroll 8
        for (int kk = 0; kk < 16; kk++) {
            float4 a0 = *(float4*)&As[cur][kk * 128 + ty * 4];
            float4 a1 = *(float4*)&As[cur][kk * 128 + 64 + ty * 4];
            ulonglong2 b0 = *(ulonglong2*)&Bs[cur][kk * 128 + tx * 4];
            ulonglong2 b1 = *(ulonglong2*)&Bs[cur][kk * 128 + 64 + tx * 4];
            ull bv[4] = {b0.x, b0.y, b1.x, b1.y};
            ull ad[8] = {dupf(a0.x), dupf(a0.y), dupf(a0.z), dupf(a0.w),
                         dupf(a1.x), dupf(a1.y), dupf(a1.z), dupf(a1.w)};
#pragma unroll
            for (int r = 0; r < 8; r++)
#pragma unroll
                for (int c = 0; c < 4; c++) ffma2(acc2[r][c], ad[r], bv[c]);
        }
        if (kt < 31) {
            const int nxt = cur ^ 1;
            *(float4*)&As[nxt][lkk0 * 128 + lc40] = pa0;
            *(float4*)&As[nxt][lkk1 * 128 + lc41] = pa1;
            *(float4*)&Bs[nxt][lkk0 * 128 + lc40] = pb0;
            *(float4*)&Bs[nxt][lkk1 * 128 + lc41] = pb1;
        }
    }

#pragma unroll
    for (int r = 0; r < 8; r++) {
        const int o = o0 + ((r < 4) ? (ty * 4 + r) : (64 + ty * 4 + r - 4));
        const float bb = bo[o];
        float* p = out + ((size_t)b * 512 + o) * 1024 + n0;
        float2 e0 = unpk(acc2[r][0]), e1 = unpk(acc2[r][1]);
        float2 e2 = unpk(acc2[r][2]), e3 = unpk(acc2[r][3]);
        *(float4*)&p[tx * 4] = make_float4(e0.x + bb, e0.y + bb, e1.x + bb, e1.y + bb);
        *(float4*)&p[64 + tx * 4] = make_float4(e2.x + bb, e2.y + bb, e3.x + bb, e3.y + bb);
    }
}

// ---------------------------------------------------------------------------
// Launch
// ---------------------------------------------------------------------------
extern "C" void kernel_launch(void* const* d_in, const int* in_sizes, int n_in,
                              void* d_out, int out_size)
{
    (void)in_sizes; (void)n_in; (void)out_size;
    const float* x     = (const float*)d_in[0];
    const float* w_q   = (const float*)d_in[1];
    const float* w_k   = (const float*)d_in[2];
    const float* w_v   = (const float*)d_in[3];
    const float* w_o   = (const float*)d_in[4];
    const float* b_o   = (const float*)d_in[5];
    const float* rel_h = (const float*)d_in[6];
    const float* rel_w = (const float*)d_in[7];
    float* out = (float*)d_out;

    cudaFuncSetAttribute(flash_kernel,
                         cudaFuncAttributeMaxDynamicSharedMemorySize,
                         FL_SMEM_BYTES);

    transpose_w_kernel<<<dim3(16, 16, 4), 256>>>(w_q, w_k, w_v, w_o);
    qkv_kernel<<<dim3(8, 4, 48), 256>>>(x);
    transpose_v_kernel<<<dim3(16, 128), 256>>>();
    flash_kernel<<<dim3(16, 128), 128, FL_SMEM_BYTES>>>(rel_h, rel_w);
    out_proj_kernel<<<dim3(8, 4, 16), 256>>>(b_o, out);
}